// round 10
// baseline (speedup 1.0000x reference)
#include <cuda_runtime.h>
#include <math.h>

#define N_TOK 2048
#define HDIM  512
#define C1    256
#define D2    1024
#define KDIM  256
#define HALFD 128
#define HEADS 4
#define SUBN  512
#define KNN   32

typedef unsigned long long u64t;

// packed fp32x2 FMA (sm_100+): d.lo += a.lo*b.lo, d.hi += a.hi*b.hi  (bit-exact fp32)
__device__ __forceinline__ u64t pack2(float lo, float hi) {
    u64t r; asm("mov.b64 %0, {%1, %2};" : "=l"(r) : "f"(lo), "f"(hi)); return r;
}
__device__ __forceinline__ void ffma2(u64t& d, u64t a, u64t b) {
    asm("fma.rn.f32x2 %0, %1, %2, %0;" : "+l"(d) : "l"(a), "l"(b));
}
__device__ __forceinline__ void unpack2(u64t v, float& lo, float& hi) {
    asm("mov.b64 {%0, %1}, %2;" : "=f"(lo), "=f"(hi) : "l"(v));
}

// ---------------- static device scratch (no allocations allowed) ----------------
__device__ float g_c1part[4 * N_TOK * C1];        // 8 MB split-K partials for gemm1
__device__ float g_q[N_TOK * D2];                 // 8 MB
__device__ float g_bn2s[D2 * 16];                 // per-(col,mblock) sums
__device__ float g_bn2q[D2 * 16];                 // per-(col,mblock) sumsq
__device__ float g_scale[KDIM];
__device__ float g_shift[KDIM];
__device__ float g_s[8u * N_TOK * SUBN];          // 32 MB scores [z][t][k]
__device__ int   g_idx[N_TOK * HEADS * KNN];
__device__ float g_w[N_TOK * HEADS * KNN];
__device__ float g_partial[N_TOK * HDIM];         // per-token gather result

// phase-2 slot table: 119 pruned pairs (i+1)*(j+1)<=32, packed (i<<8)|j
__constant__ unsigned short c_pp[128] = {
    0x000,0x001,0x002,0x003,0x004,0x005,0x006,0x007,
    0x008,0x009,0x00A,0x00B,0x00C,0x00D,0x00E,0x00F,
    0x010,0x011,0x012,0x013,0x014,0x015,0x016,0x017,
    0x018,0x019,0x01A,0x01B,0x01C,0x01D,0x01E,0x01F,
    0x100,0x101,0x102,0x103,0x104,0x105,0x106,0x107,
    0x108,0x109,0x10A,0x10B,0x10C,0x10D,0x10E,0x10F,
    0x200,0x201,0x202,0x203,0x204,0x205,0x206,0x207,0x208,0x209,
    0x300,0x301,0x302,0x303,0x304,0x305,0x306,0x307,
    0x400,0x401,0x402,0x403,0x404,0x405,
    0x500,0x501,0x502,0x503,0x504,
    0x600,0x601,0x602,0x603,
    0x700,0x701,0x702,0x703,
    0x800,0x801,0x802,
    0x900,0x901,0x902,
    0xA00,0xA01,0xB00,0xB01,0xC00,0xC01,0xD00,0xD01,0xE00,0xE01,0xF00,0xF01,
    0x1000,0x1100,0x1200,0x1300,0x1400,0x1500,0x1600,0x1700,
    0x1800,0x1900,0x1A00,0x1B00,0x1C00,0x1D00,0x1E00,0x1F00,
    0,0,0,0,0,0,0,0,0
};

// order-preserving float<->uint transform
__device__ __forceinline__ unsigned int ordu(float f) {
    int s = __float_as_int(f);
    return (unsigned int)(s ^ ((s >> 31) | 0x80000000));
}
__device__ __forceinline__ float unordu(unsigned int u) {
    int s = (u & 0x80000000u) ? (int)(u ^ 0x80000000u) : (int)~u;
    return __int_as_float(s);
}

// =====================================================================================
// 128x128 tile SGEMM, 256 threads, 8x8 microtile via FFMA2, BK=16.
// 2-stage smem double buffer: ONE __syncthreads per k-tile (stores go to the idle
// buffer). a-frag loaded as LDS.128 + register repack (mov.b64) -> 4 LDS per k-step.
// __launch_bounds__(256,2): 2 CTAs/SM.
// =====================================================================================
template<int K, int LDA, int LDB, bool HASBIAS, bool NORM>
__global__ void __launch_bounds__(256, 2) sgemm128(const float* __restrict__ A,
                                                   const float* __restrict__ B,
                                                   const float* __restrict__ bias,
                                                   float* __restrict__ C,
                                                   int ldc, int aZ, int bZ, size_t cZ)
{
    __shared__ float As[2][16][132];
    __shared__ float Bs[2][16][132];
    const int tid = threadIdx.x;
    const int z = blockIdx.z;
    const int bm = blockIdx.x * 128, bn = blockIdx.y * 128;
    A += (size_t)z * aZ;
    B += (size_t)z * bZ;
    C += (size_t)z * cZ;

    const int lrow = tid >> 1;
    const int lkc  = (tid & 1) << 3;
    const float* Aptr = A + (size_t)(bm + lrow) * LDA + lkc;
    const float* Bptr = B + (size_t)(bn + lrow) * LDB + lkc;

    const int w = tid >> 5, lane = tid & 31;
    const int wr = w & 3, wc = w >> 2;
    const int row0 = (wr << 5) + ((lane & 3) << 3);    // 0..120
    const int col0 = (wc << 6) + ((lane >> 2) << 3);   // 0..120

    u64t acc2[8][4];
#pragma unroll
    for (int j = 0; j < 8; j++)
#pragma unroll
        for (int p = 0; p < 4; p++) acc2[j][p] = 0ull;

    float4 a0, a1, b0, b1;

    a0 = *(const float4*)(Aptr);     a1 = *(const float4*)(Aptr + 4);
    b0 = *(const float4*)(Bptr);     b1 = *(const float4*)(Bptr + 4);
    if (NORM) {
        const int dk = ((z & 1) << 7) + lkc;
        float4 sc0 = *(const float4*)(g_scale + dk), sh0 = *(const float4*)(g_shift + dk);
        float4 sc1 = *(const float4*)(g_scale + dk + 4), sh1 = *(const float4*)(g_shift + dk + 4);
        a0.x = fmaf(a0.x, sc0.x, sh0.x); a0.y = fmaf(a0.y, sc0.y, sh0.y);
        a0.z = fmaf(a0.z, sc0.z, sh0.z); a0.w = fmaf(a0.w, sc0.w, sh0.w);
        a1.x = fmaf(a1.x, sc1.x, sh1.x); a1.y = fmaf(a1.y, sc1.y, sh1.y);
        a1.z = fmaf(a1.z, sc1.z, sh1.z); a1.w = fmaf(a1.w, sc1.w, sh1.w);
    }
    As[0][lkc+0][lrow]=a0.x; As[0][lkc+1][lrow]=a0.y; As[0][lkc+2][lrow]=a0.z; As[0][lkc+3][lrow]=a0.w;
    As[0][lkc+4][lrow]=a1.x; As[0][lkc+5][lrow]=a1.y; As[0][lkc+6][lrow]=a1.z; As[0][lkc+7][lrow]=a1.w;
    Bs[0][lkc+0][lrow]=b0.x; Bs[0][lkc+1][lrow]=b0.y; Bs[0][lkc+2][lrow]=b0.z; Bs[0][lkc+3][lrow]=b0.w;
    Bs[0][lkc+4][lrow]=b1.x; Bs[0][lkc+5][lrow]=b1.y; Bs[0][lkc+6][lrow]=b1.z; Bs[0][lkc+7][lrow]=b1.w;
    __syncthreads();

    int pb = 0;
#pragma unroll 1
    for (int kb = 1; kb <= K / 16; kb++) {
        const bool more = kb < K / 16;
        if (more) {
            const int k0 = kb * 16;
            a0 = *(const float4*)(Aptr + k0);     a1 = *(const float4*)(Aptr + k0 + 4);
            b0 = *(const float4*)(Bptr + k0);     b1 = *(const float4*)(Bptr + k0 + 4);
            if (NORM) {
                const int dk = ((z & 1) << 7) + lkc + k0;
                float4 sc0 = *(const float4*)(g_scale + dk), sh0 = *(const float4*)(g_shift + dk);
                float4 sc1 = *(const float4*)(g_scale + dk + 4), sh1 = *(const float4*)(g_shift + dk + 4);
                a0.x = fmaf(a0.x, sc0.x, sh0.x); a0.y = fmaf(a0.y, sc0.y, sh0.y);
                a0.z = fmaf(a0.z, sc0.z, sh0.z); a0.w = fmaf(a0.w, sc0.w, sh0.w);
                a1.x = fmaf(a1.x, sc1.x, sh1.x); a1.y = fmaf(a1.y, sc1.y, sh1.y);
                a1.z = fmaf(a1.z, sc1.z, sh1.z); a1.w = fmaf(a1.w, sc1.w, sh1.w);
            }
        }
#pragma unroll
        for (int k = 0; k < 16; k++) {
            // a-frag: 2x LDS.128, repack to u64 pairs in registers (alu movs)
            float4 af0 = *(const float4*)&As[pb][k][row0];
            float4 af1 = *(const float4*)&As[pb][k][row0 + 4];
            const u64t apair0 = pack2(af0.x, af0.y);
            const u64t apair1 = pack2(af0.z, af0.w);
            const u64t apair2 = pack2(af1.x, af1.y);
            const u64t apair3 = pack2(af1.z, af1.w);
            float4 bf0 = *(const float4*)&Bs[pb][k][col0];
            float4 bf1 = *(const float4*)&Bs[pb][k][col0 + 4];
            const float br[8] = {bf0.x,bf0.y,bf0.z,bf0.w,bf1.x,bf1.y,bf1.z,bf1.w};
#pragma unroll
            for (int j = 0; j < 8; j++) {
                const u64t bs = pack2(br[j], br[j]);
                ffma2(acc2[j][0], apair0, bs);
                ffma2(acc2[j][1], apair1, bs);
                ffma2(acc2[j][2], apair2, bs);
                ffma2(acc2[j][3], apair3, bs);
            }
        }
        if (more) {
            // store into the idle buffer — no barrier needed before these stores
            const int pn = pb ^ 1;
            As[pn][lkc+0][lrow]=a0.x; As[pn][lkc+1][lrow]=a0.y; As[pn][lkc+2][lrow]=a0.z; As[pn][lkc+3][lrow]=a0.w;
            As[pn][lkc+4][lrow]=a1.x; As[pn][lkc+5][lrow]=a1.y; As[pn][lkc+6][lrow]=a1.z; As[pn][lkc+7][lrow]=a1.w;
            Bs[pn][lkc+0][lrow]=b0.x; Bs[pn][lkc+1][lrow]=b0.y; Bs[pn][lkc+2][lrow]=b0.z; Bs[pn][lkc+3][lrow]=b0.w;
            Bs[pn][lkc+4][lrow]=b1.x; Bs[pn][lkc+5][lrow]=b1.y; Bs[pn][lkc+6][lrow]=b1.z; Bs[pn][lkc+7][lrow]=b1.w;
            __syncthreads();
            pb = pn;
        }
    }

    float acc[8][8];
#pragma unroll
    for (int j = 0; j < 8; j++)
#pragma unroll
        for (int p = 0; p < 4; p++)
            unpack2(acc2[j][p], acc[2*p][j], acc[2*p+1][j]);

    float4 bb0 = {0,0,0,0}, bb1 = {0,0,0,0};
    if (HASBIAS) {
        bb0 = *(const float4*)(bias + bn + col0);
        bb1 = *(const float4*)(bias + bn + col0 + 4);
    }
#pragma unroll
    for (int i = 0; i < 8; i++) {
        const int r = bm + row0 + i;
        float4 o0 = { acc[i][0] + bb0.x, acc[i][1] + bb0.y, acc[i][2] + bb0.z, acc[i][3] + bb0.w };
        float4 o1 = { acc[i][4] + bb1.x, acc[i][5] + bb1.y, acc[i][6] + bb1.z, acc[i][7] + bb1.w };
        *(float4*)(C + (size_t)r * ldc + bn + col0)     = o0;
        *(float4*)(C + (size_t)r * ldc + bn + col0 + 4) = o1;
    }
}

// =====================================================================================
// gemm2 fused (scalar FFMA mainloop — measured best): A = relu(sum 4 partials + b1),
// C = A @ w2^T + b2 -> g_q, epilogue computes per-block BN column sums/sumsq.
// =====================================================================================
__global__ void __launch_bounds__(256) gemm2_fused(const float* __restrict__ b1,
                                                   const float* __restrict__ w2,
                                                   const float* __restrict__ b2)
{
    __shared__ float As[16][132];
    __shared__ float Bs[16][132];
    __shared__ float red[16][128];
    const int tid = threadIdx.x;
    const int bm = blockIdx.x * 128, bn = blockIdx.y * 128;

    const int lrow = tid >> 1;
    const int lkc  = (tid & 1) << 3;
    const size_t pstride = (size_t)N_TOK * C1;
    const float* Pptr = g_c1part + (size_t)(bm + lrow) * C1 + lkc;
    const float* Bptr = w2 + (size_t)(bn + lrow) * C1 + lkc;

    const int w = tid >> 5, lane = tid & 31;
    const int wr = w & 3, wc = w >> 2;
    const int row0 = (wr << 5) + ((lane & 3) << 3);
    const int col0 = (wc << 6) + ((lane >> 2) << 3);

    float acc[8][8] = {};
    float4 a0, a1, b0, b1v;

    auto loadA = [&](int k0, float4& o0, float4& o1) {
        const float* p = Pptr + k0;
        float4 u0 = *(const float4*)(p);
        float4 u1 = *(const float4*)(p + 4);
        float4 v0 = *(const float4*)(p + pstride);
        float4 v1 = *(const float4*)(p + pstride + 4);
        float4 x0 = *(const float4*)(p + 2*pstride);
        float4 x1 = *(const float4*)(p + 2*pstride + 4);
        float4 y0 = *(const float4*)(p + 3*pstride);
        float4 y1 = *(const float4*)(p + 3*pstride + 4);
        float4 c0 = *(const float4*)(b1 + k0 + lkc);
        float4 c1 = *(const float4*)(b1 + k0 + lkc + 4);
        o0.x = fmaxf((u0.x+v0.x)+(x0.x+y0.x)+c0.x, 0.f);
        o0.y = fmaxf((u0.y+v0.y)+(x0.y+y0.y)+c0.y, 0.f);
        o0.z = fmaxf((u0.z+v0.z)+(x0.z+y0.z)+c0.z, 0.f);
        o0.w = fmaxf((u0.w+v0.w)+(x0.w+y0.w)+c0.w, 0.f);
        o1.x = fmaxf((u1.x+v1.x)+(x1.x+y1.x)+c1.x, 0.f);
        o1.y = fmaxf((u1.y+v1.y)+(x1.y+y1.y)+c1.y, 0.f);
        o1.z = fmaxf((u1.z+v1.z)+(x1.z+y1.z)+c1.z, 0.f);
        o1.w = fmaxf((u1.w+v1.w)+(x1.w+y1.w)+c1.w, 0.f);
    };

    loadA(0, a0, a1);
    b0 = *(const float4*)(Bptr);     b1v = *(const float4*)(Bptr + 4);
    As[lkc+0][lrow]=a0.x; As[lkc+1][lrow]=a0.y; As[lkc+2][lrow]=a0.z; As[lkc+3][lrow]=a0.w;
    As[lkc+4][lrow]=a1.x; As[lkc+5][lrow]=a1.y; As[lkc+6][lrow]=a1.z; As[lkc+7][lrow]=a1.w;
    Bs[lkc+0][lrow]=b0.x; Bs[lkc+1][lrow]=b0.y; Bs[lkc+2][lrow]=b0.z; Bs[lkc+3][lrow]=b0.w;
    Bs[lkc+4][lrow]=b1v.x; Bs[lkc+5][lrow]=b1v.y; Bs[lkc+6][lrow]=b1v.z; Bs[lkc+7][lrow]=b1v.w;
    __syncthreads();

#pragma unroll 1
    for (int kb = 1; kb <= C1 / 16; kb++) {
        const bool more = kb < C1 / 16;
        if (more) {
            const int k0 = kb * 16;
            loadA(k0, a0, a1);
            b0 = *(const float4*)(Bptr + k0);     b1v = *(const float4*)(Bptr + k0 + 4);
        }
#pragma unroll
        for (int k = 0; k < 16; k++) {
            float4 af0 = *(const float4*)&As[k][row0];
            float4 af1 = *(const float4*)&As[k][row0 + 4];
            float4 bf0 = *(const float4*)&Bs[k][col0];
            float4 bf1 = *(const float4*)&Bs[k][col0 + 4];
            const float ar[8] = {af0.x,af0.y,af0.z,af0.w,af1.x,af1.y,af1.z,af1.w};
            const float br[8] = {bf0.x,bf0.y,bf0.z,bf0.w,bf1.x,bf1.y,bf1.z,bf1.w};
#pragma unroll
            for (int i = 0; i < 8; i++)
#pragma unroll
                for (int j = 0; j < 8; j++)
                    acc[i][j] = fmaf(ar[i], br[j], acc[i][j]);
        }
        if (more) {
            __syncthreads();
            As[lkc+0][lrow]=a0.x; As[lkc+1][lrow]=a0.y; As[lkc+2][lrow]=a0.z; As[lkc+3][lrow]=a0.w;
            As[lkc+4][lrow]=a1.x; As[lkc+5][lrow]=a1.y; As[lkc+6][lrow]=a1.z; As[lkc+7][lrow]=a1.w;
            Bs[lkc+0][lrow]=b0.x; Bs[lkc+1][lrow]=b0.y; Bs[lkc+2][lrow]=b0.z; Bs[lkc+3][lrow]=b0.w;
            Bs[lkc+4][lrow]=b1v.x; Bs[lkc+5][lrow]=b1v.y; Bs[lkc+6][lrow]=b1v.z; Bs[lkc+7][lrow]=b1v.w;
            __syncthreads();
        }
    }

    float4 bb0 = *(const float4*)(b2 + bn + col0);
    float4 bb1 = *(const float4*)(b2 + bn + col0 + 4);
    float ps[8] = {}, ps2[8] = {};
#pragma unroll
    for (int i = 0; i < 8; i++) {
        const int r = bm + row0 + i;
        float4 o0 = { acc[i][0] + bb0.x, acc[i][1] + bb0.y, acc[i][2] + bb0.z, acc[i][3] + bb0.w };
        float4 o1 = { acc[i][4] + bb1.x, acc[i][5] + bb1.y, acc[i][6] + bb1.z, acc[i][7] + bb1.w };
        *(float4*)(g_q + (size_t)r * D2 + bn + col0)     = o0;
        *(float4*)(g_q + (size_t)r * D2 + bn + col0 + 4) = o1;
        ps[0] += o0.x; ps[1] += o0.y; ps[2] += o0.z; ps[3] += o0.w;
        ps[4] += o1.x; ps[5] += o1.y; ps[6] += o1.z; ps[7] += o1.w;
        ps2[0] += o0.x*o0.x; ps2[1] += o0.y*o0.y; ps2[2] += o0.z*o0.z; ps2[3] += o0.w*o0.w;
        ps2[4] += o1.x*o1.x; ps2[5] += o1.y*o1.y; ps2[6] += o1.z*o1.z; ps2[7] += o1.w*o1.w;
    }

    const int rrank = (wr << 2) | (lane & 3);
    __syncthreads();
#pragma unroll
    for (int j = 0; j < 8; j++) red[rrank][col0 + j] = ps[j];
    __syncthreads();
    if (tid < 128) {
        float v = 0.f;
#pragma unroll
        for (int r = 0; r < 16; r++) v += red[r][tid];
        g_bn2s[(size_t)(bn + tid) * 16 + blockIdx.x] = v;
    }
    __syncthreads();
#pragma unroll
    for (int j = 0; j < 8; j++) red[rrank][col0 + j] = ps2[j];
    __syncthreads();
    if (tid < 128) {
        float v = 0.f;
#pragma unroll
        for (int r = 0; r < 16; r++) v += red[r][tid];
        g_bn2q[(size_t)(bn + tid) * 16 + blockIdx.x] = v;
    }
}

// ---------------- BN finalize: fold 16 m-blocks x 4 head-columns ----------------
__global__ void __launch_bounds__(64) bn_finalize(const float* __restrict__ gamma,
                                                  const float* __restrict__ beta)
{
    const int d = blockIdx.x, t = threadIdx.x;
    const int hh = t >> 4, bi = t & 15;
    const int col = d + (hh << 8);
    float s  = g_bn2s[(size_t)col * 16 + bi];
    float s2 = g_bn2q[(size_t)col * 16 + bi];
#pragma unroll
    for (int o = 16; o > 0; o >>= 1) {
        s  += __shfl_xor_sync(0xffffffffu, s, o);
        s2 += __shfl_xor_sync(0xffffffffu, s2, o);
    }
    __shared__ float r1[2], r2[2];
    if ((t & 31) == 0) { r1[t >> 5] = s; r2[t >> 5] = s2; }
    __syncthreads();
    if (t == 0) {
        s  = r1[0] + r1[1];
        s2 = r2[0] + r2[1];
        const float inv = 1.0f / 8192.0f;
        float mean = s * inv;
        float var  = s2 * inv - mean * mean;
        float sc = rsqrtf(var + 1e-5f) * gamma[d];
        g_scale[d] = sc;
        g_shift[d] = beta[d] - mean * sc;
    }
}

// ---------------- two-level top-k + softmax (REDUX tournament) ----------------
__global__ void __launch_bounds__(64) topk_kernel()
{
    const int b = blockIdx.x;
    const int t = b >> 2, h = b & 3;
    const int w = threadIdx.x >> 5;
    const int lane = threadIdx.x & 31;

    __shared__ float sts[2][32];
    __shared__ int   sti[2][32];

    {
        const float* row = g_s + ((size_t)(h * 2 + w) * N_TOK + t) * SUBN;
        unsigned int v[16];
#pragma unroll
        for (int c = 0; c < 16; c++) v[c] = ordu(row[lane + 32 * c]);

        for (int it = 0; it < 32; it++) {
            unsigned int lm = v[0]; int lc = 0;
#pragma unroll
            for (int c = 1; c < 16; c++) if (v[c] > lm) { lm = v[c]; lc = c; }
            const unsigned int wm = __reduce_max_sync(0xffffffffu, lm);
            const unsigned int myidx = (lm == wm) ? (unsigned int)(lane + (lc << 5)) : 0xffffffffu;
            const unsigned int wi = __reduce_min_sync(0xffffffffu, myidx);
            if (lane == it) { sts[w][it] = unordu(wm); sti[w][it] = (int)wi; }
            if (lane == (int)(wi & 31)) {
                const int cc = (int)(wi >> 5);
#pragma unroll
                for (int c = 0; c < 16; c++) if (c == cc) v[c] = 0u;
            }
        }
    }
    __syncthreads();

    if (w == 0) {
        unsigned int key[4];
        unsigned int flt[4];
#pragma unroll
        for (int q = 0; q < 4; q++) {
            const int s = lane + (q << 5);
            const int pp = c_pp[s];
            const int i = pp >> 8, j = pp & 0xff;
            const float sum = sts[0][i] + sts[1][j];
            key[q] = (s < 119) ? ordu(sum) : 0u;
            flt[q] = (unsigned int)((i << 5) | j);
        }

        unsigned int selu = 0, self = 0;
        for (int it = 0; it < 32; it++) {
            unsigned int lm = key[0], lf = flt[0]; int lq = 0;
#pragma unroll
            for (int q = 1; q < 4; q++) {
                if (key[q] > lm || (key[q] == lm && flt[q] < lf)) { lm = key[q]; lf = flt[q]; lq = q; }
            }
            const unsigned int wm = __reduce_max_sync(0xffffffffu, lm);
            const unsigned int mf = (lm == wm) ? lf : 0xffffffffu;
            const unsigned int wf = __reduce_min_sync(0xffffffffu, mf);
            if (lane == it) { selu = wm; self = wf; }
            if (lm == wm && lf == wf) {
#pragma unroll
                for (int q = 0; q < 4; q++) if (q == lq) key[q] = 0u;
            }
        }

        const float myv = unordu(selu);
        const int i = (int)(self >> 5), j = (int)(self & 31);
        const int idx = sti[0][i] * SUBN + sti[1][j];

        const float mx = __shfl_sync(0xffffffffu, myv, 0);
        float e = expf(myv - mx);
        float sum = e;
#pragma unroll
        for (int o = 16; o > 0; o >>= 1) sum += __shfl_xor_sync(0xffffffffu, sum, o);
        const size_t oo = (size_t)t * (HEADS * KNN) + h * KNN + lane;
        g_idx[oo] = idx;
        g_w[oo]   = e / sum;
    }
}

// ---------------- weighted gather from values table (MLP=8) ----------------
__global__ void __launch_bounds__(128) gather_kernel(const float* __restrict__ values)
{
    const int t = blockIdx.x;
    const int tid = threadIdx.x;
    __shared__ int   sidx[128];
    __shared__ float sw[128];
    sidx[tid] = g_idx[(size_t)t * 128 + tid];
    sw[tid]   = g_w[(size_t)t * 128 + tid];
    __syncthreads();

    const int col = tid << 2;
    float4 a0 = {0,0,0,0}, a1 = {0,0,0,0}, a2 = {0,0,0,0}, a3 = {0,0,0,0};
    float4 a4 = {0,0,0,0}, a5 = {0,0,0,0}, a6 = {0,0,0,0}, a7 = {0,0,0,0};
#pragma unroll
    for (int k = 0; k < 128; k += 8) {
        const float4 v0 = *(const float4*)(values + (size_t)sidx[k + 0] * HDIM + col);
        const float4 v1 = *(const float4*)(values + (size_t)sidx[k + 1] * HDIM + col);
        const float4 v2 = *(const float4*)(values + (size_t)sidx[k + 2] * HDIM + col);
        const float4 v3 = *(const float4*)(values + (size_t)sidx[k + 3] * HDIM + col);
        const float4 v4 = *(const float4*)(values + (size_t)sidx[k + 4] * HDIM + col);
        const float4 v5 = *(const float4*)(values + (size_t)sidx[k + 5] * HDIM + col);
        const float4 v6 = *(const float4*)(values + (size_t)sidx[k + 6] * HDIM + col);
        const float4 v7 = *(const float4*)(values + (size_t)sidx[k + 7] * HDIM + col);
        const float w0 = sw[k+0], w1 = sw[k+1], w2 = sw[k+2], w3 = sw[k+3];
        const float w4 = sw[k+4], w5 = sw[k+5], w6 = sw[k+6], w7 = sw[k+7];
        a0.x += w0*v0.x; a0.y += w0*v0.y; a0.z += w0*v0.z; a0.w += w0*v0.w;
        a1.x += w1*v1.x; a1.y += w1*v1.y; a1.z += w1*v1.z; a1.w += w1*v1.w;
        a2.x += w2*v2.x; a2.y += w2*v2.y; a2.z += w2*v2.z; a2.w += w2*v2.w;
        a3.x += w3*v3.x; a3.y += w3*v3.y; a3.z += w3*v3.z; a3.w += w3*v3.w;
        a4.x += w4*v4.x; a4.y += w4*v4.y; a4.z += w4*v4.z; a4.w += w4*v4.w;
        a5.x += w5*v5.x; a5.y += w5*v5.y; a5.z += w5*v5.z; a5.w += w5*v5.w;
        a6.x += w6*v6.x; a6.y += w6*v6.y; a6.z += w6*v6.z; a6.w += w6*v6.w;
        a7.x += w7*v7.x; a7.y += w7*v7.y; a7.z += w7*v7.z; a7.w += w7*v7.w;
    }
    float4 acc;
    acc.x = ((a0.x + a1.x) + (a2.x + a3.x)) + ((a4.x + a5.x) + (a6.x + a7.x));
    acc.y = ((a0.y + a1.y) + (a2.y + a3.y)) + ((a4.y + a5.y) + (a6.y + a7.y));
    acc.z = ((a0.z + a1.z) + (a2.z + a3.z)) + ((a4.z + a5.z) + (a6.z + a7.z));
    acc.w = ((a0.w + a1.w) + (a2.w + a3.w)) + ((a4.w + a5.w) + (a6.w + a7.w));
    *(float4*)(g_partial + (size_t)t * HDIM + col) = acc;
}

// ---------------- deterministic reduce over sequence ----------------
__global__ void __launch_bounds__(512) reduce_kernel(float* __restrict__ out)
{
    const int e = blockIdx.x * 512 + threadIdx.x;
    const int bb = e >> 9, c = e & 511;
    float s0 = 0.f, s1 = 0.f, s2 = 0.f, s3 = 0.f;
#pragma unroll
    for (int l = 0; l < 64; l += 4) {
        s0 += g_partial[(size_t)((bb << 6) + l + 0) * HDIM + c];
        s1 += g_partial[(size_t)((bb << 6) + l + 1) * HDIM + c];
        s2 += g_partial[(size_t)((bb << 6) + l + 2) * HDIM + c];
        s3 += g_partial[(size_t)((bb << 6) + l + 3) * HDIM + c];
    }
    out[e] = (s0 + s1) + (s2 + s3);
}

// ---------------- launch ----------------
extern "C" void kernel_launch(void* const* d_in, const int* in_sizes, int n_in,
                              void* d_out, int out_size)
{
    (void)in_sizes; (void)n_in; (void)out_size;
    const float* x        = (const float*)d_in[0];
    const float* w1       = (const float*)d_in[1];
    const float* b1       = (const float*)d_in[2];
    const float* w2       = (const float*)d_in[3];
    const float* b2       = (const float*)d_in[4];
    const float* bn_gamma = (const float*)d_in[5];
    const float* bn_beta  = (const float*)d_in[6];
    const float* keys     = (const float*)d_in[7];
    const float* values   = (const float*)d_in[8];
    float* out = (float*)d_out;

    float *d_q, *d_c1, *d_s;
    cudaGetSymbolAddress((void**)&d_q, g_q);
    cudaGetSymbolAddress((void**)&d_c1, g_c1part);
    cudaGetSymbolAddress((void**)&d_s, g_s);

    // 1) gemm1 split-K=4 -> partials [4][2048x256]
    sgemm128<128, HDIM, HDIM, false, false>
        <<<dim3(16, 2, 4), 256>>>(x, w1, nullptr, d_c1, C1, 128, 128, (size_t)N_TOK * C1);
    // 2) gemm2 fused (combine+relu on A, BN partials in epilogue) -> g_q
    gemm2_fused<<<dim3(16, 8), 256>>>(b1, w2, b2);
    // 3) BN finalize
    bn_finalize<<<KDIM, 64>>>(bn_gamma, bn_beta);
    // 4) scores with fused BN normalize  [8][2048][512]   <-- profiled slot
    sgemm128<HALFD, D2, HALFD, false, true>
        <<<dim3(16, 4, 8), 256>>>(d_q, keys, nullptr, d_s, SUBN,
                                  128, SUBN * HALFD, (size_t)N_TOK * SUBN);
    // 5) two-level top-k + softmax
    topk_kernel<<<N_TOK * HEADS, 64>>>();
    // 6) weighted gather
    gather_kernel<<<N_TOK, 128>>>(values);
    // 7) sum over sequence
    reduce_kernel<<<32, 512>>>(out);
}

// round 11
// speedup vs baseline: 1.1299x; 1.1299x over previous
#include <cuda_runtime.h>
#include <math.h>

#define N_TOK 2048
#define HDIM  512
#define C1    256
#define D2    1024
#define KDIM  256
#define HALFD 128
#define HEADS 4
#define SUBN  512
#define KNN   32

typedef unsigned long long u64t;

// packed fp32x2 FMA (sm_100+): d.lo += a.lo*b.lo, d.hi += a.hi*b.hi  (bit-exact fp32)
__device__ __forceinline__ u64t pack2(float lo, float hi) {
    u64t r; asm("mov.b64 %0, {%1, %2};" : "=l"(r) : "f"(lo), "f"(hi)); return r;
}
__device__ __forceinline__ void ffma2(u64t& d, u64t a, u64t b) {
    asm("fma.rn.f32x2 %0, %1, %2, %0;" : "+l"(d) : "l"(a), "l"(b));
}
__device__ __forceinline__ void unpack2(u64t v, float& lo, float& hi) {
    asm("mov.b64 {%0, %1}, %2;" : "=f"(lo), "=f"(hi) : "l"(v));
}

// ---------------- static device scratch (no allocations allowed) ----------------
__device__ float g_c1part[4 * N_TOK * C1];        // 8 MB split-K partials for gemm1
__device__ float g_q[N_TOK * D2];                 // 8 MB
__device__ float g_bn2s[D2 * 16];                 // per-(col,mblock) sums
__device__ float g_bn2q[D2 * 16];                 // per-(col,mblock) sumsq
__device__ float g_scale[KDIM];
__device__ float g_shift[KDIM];
__device__ float g_s[8u * N_TOK * SUBN];          // 32 MB scores [z][t][k]
__device__ int   g_idx[N_TOK * HEADS * KNN];
__device__ float g_w[N_TOK * HEADS * KNN];
__device__ float g_partial[N_TOK * HDIM];         // per-token gather result

// phase-2 slot table: 119 pruned pairs (i+1)*(j+1)<=32, packed (i<<8)|j
__constant__ unsigned short c_pp[128] = {
    0x000,0x001,0x002,0x003,0x004,0x005,0x006,0x007,
    0x008,0x009,0x00A,0x00B,0x00C,0x00D,0x00E,0x00F,
    0x010,0x011,0x012,0x013,0x014,0x015,0x016,0x017,
    0x018,0x019,0x01A,0x01B,0x01C,0x01D,0x01E,0x01F,
    0x100,0x101,0x102,0x103,0x104,0x105,0x106,0x107,
    0x108,0x109,0x10A,0x10B,0x10C,0x10D,0x10E,0x10F,
    0x200,0x201,0x202,0x203,0x204,0x205,0x206,0x207,0x208,0x209,
    0x300,0x301,0x302,0x303,0x304,0x305,0x306,0x307,
    0x400,0x401,0x402,0x403,0x404,0x405,
    0x500,0x501,0x502,0x503,0x504,
    0x600,0x601,0x602,0x603,
    0x700,0x701,0x702,0x703,
    0x800,0x801,0x802,
    0x900,0x901,0x902,
    0xA00,0xA01,0xB00,0xB01,0xC00,0xC01,0xD00,0xD01,0xE00,0xE01,0xF00,0xF01,
    0x1000,0x1100,0x1200,0x1300,0x1400,0x1500,0x1600,0x1700,
    0x1800,0x1900,0x1A00,0x1B00,0x1C00,0x1D00,0x1E00,0x1F00,
    0,0,0,0,0,0,0,0,0
};

// order-preserving float<->uint transform
__device__ __forceinline__ unsigned int ordu(float f) {
    int s = __float_as_int(f);
    return (unsigned int)(s ^ ((s >> 31) | 0x80000000));
}
__device__ __forceinline__ float unordu(unsigned int u) {
    int s = (u & 0x80000000u) ? (int)(u ^ 0x80000000u) : (int)~u;
    return __int_as_float(s);
}

// =====================================================================================
// 128x128 tile SGEMM (R9 measured-best): 256 threads, 8x8 microtile via FFMA2, BK=16,
// single-buffered smem, conflict-free 32x64 warp tile, __launch_bounds__(256,2).
// =====================================================================================
template<int K, int LDA, int LDB, bool HASBIAS, bool NORM>
__global__ void __launch_bounds__(256, 2) sgemm128(const float* __restrict__ A,
                                                   const float* __restrict__ B,
                                                   const float* __restrict__ bias,
                                                   float* __restrict__ C,
                                                   int ldc, int aZ, int bZ, size_t cZ)
{
    __shared__ float As[16][132];
    __shared__ float Bs[16][132];
    const int tid = threadIdx.x;
    const int z = blockIdx.z;
    const int bm = blockIdx.x * 128, bn = blockIdx.y * 128;
    A += (size_t)z * aZ;
    B += (size_t)z * bZ;
    C += (size_t)z * cZ;

    const int lrow = tid >> 1;
    const int lkc  = (tid & 1) << 3;
    const float* Aptr = A + (size_t)(bm + lrow) * LDA + lkc;
    const float* Bptr = B + (size_t)(bn + lrow) * LDB + lkc;

    const int w = tid >> 5, lane = tid & 31;
    const int wr = w & 3, wc = w >> 2;
    const int row0 = (wr << 5) + ((lane & 3) << 3);    // 0..120
    const int col0 = (wc << 6) + ((lane >> 2) << 3);   // 0..120

    u64t acc2[8][4];
#pragma unroll
    for (int j = 0; j < 8; j++)
#pragma unroll
        for (int p = 0; p < 4; p++) acc2[j][p] = 0ull;

    float4 a0, a1, b0, b1;

    a0 = *(const float4*)(Aptr);     a1 = *(const float4*)(Aptr + 4);
    b0 = *(const float4*)(Bptr);     b1 = *(const float4*)(Bptr + 4);
    if (NORM) {
        const int dk = ((z & 1) << 7) + lkc;
        float4 sc0 = *(const float4*)(g_scale + dk), sh0 = *(const float4*)(g_shift + dk);
        float4 sc1 = *(const float4*)(g_scale + dk + 4), sh1 = *(const float4*)(g_shift + dk + 4);
        a0.x = fmaf(a0.x, sc0.x, sh0.x); a0.y = fmaf(a0.y, sc0.y, sh0.y);
        a0.z = fmaf(a0.z, sc0.z, sh0.z); a0.w = fmaf(a0.w, sc0.w, sh0.w);
        a1.x = fmaf(a1.x, sc1.x, sh1.x); a1.y = fmaf(a1.y, sc1.y, sh1.y);
        a1.z = fmaf(a1.z, sc1.z, sh1.z); a1.w = fmaf(a1.w, sc1.w, sh1.w);
    }
    As[lkc+0][lrow]=a0.x; As[lkc+1][lrow]=a0.y; As[lkc+2][lrow]=a0.z; As[lkc+3][lrow]=a0.w;
    As[lkc+4][lrow]=a1.x; As[lkc+5][lrow]=a1.y; As[lkc+6][lrow]=a1.z; As[lkc+7][lrow]=a1.w;
    Bs[lkc+0][lrow]=b0.x; Bs[lkc+1][lrow]=b0.y; Bs[lkc+2][lrow]=b0.z; Bs[lkc+3][lrow]=b0.w;
    Bs[lkc+4][lrow]=b1.x; Bs[lkc+5][lrow]=b1.y; Bs[lkc+6][lrow]=b1.z; Bs[lkc+7][lrow]=b1.w;
    __syncthreads();

#pragma unroll 1
    for (int kb = 1; kb <= K / 16; kb++) {
        const bool more = kb < K / 16;
        if (more) {
            const int k0 = kb * 16;
            a0 = *(const float4*)(Aptr + k0);     a1 = *(const float4*)(Aptr + k0 + 4);
            b0 = *(const float4*)(Bptr + k0);     b1 = *(const float4*)(Bptr + k0 + 4);
            if (NORM) {
                const int dk = ((z & 1) << 7) + lkc + k0;
                float4 sc0 = *(const float4*)(g_scale + dk), sh0 = *(const float4*)(g_shift + dk);
                float4 sc1 = *(const float4*)(g_scale + dk + 4), sh1 = *(const float4*)(g_shift + dk + 4);
                a0.x = fmaf(a0.x, sc0.x, sh0.x); a0.y = fmaf(a0.y, sc0.y, sh0.y);
                a0.z = fmaf(a0.z, sc0.z, sh0.z); a0.w = fmaf(a0.w, sc0.w, sh0.w);
                a1.x = fmaf(a1.x, sc1.x, sh1.x); a1.y = fmaf(a1.y, sc1.y, sh1.y);
                a1.z = fmaf(a1.z, sc1.z, sh1.z); a1.w = fmaf(a1.w, sc1.w, sh1.w);
            }
        }
#pragma unroll
        for (int k = 0; k < 16; k++) {
            const u64t* ap0 = (const u64t*)&As[k][row0];
            const u64t* ap1 = (const u64t*)&As[k][row0 + 4];
            const u64t apair0 = ap0[0], apair1 = ap0[1], apair2 = ap1[0], apair3 = ap1[1];
            float4 bf0 = *(const float4*)&Bs[k][col0];
            float4 bf1 = *(const float4*)&Bs[k][col0 + 4];
            const float br[8] = {bf0.x,bf0.y,bf0.z,bf0.w,bf1.x,bf1.y,bf1.z,bf1.w};
#pragma unroll
            for (int j = 0; j < 8; j++) {
                const u64t bs = pack2(br[j], br[j]);
                ffma2(acc2[j][0], apair0, bs);
                ffma2(acc2[j][1], apair1, bs);
                ffma2(acc2[j][2], apair2, bs);
                ffma2(acc2[j][3], apair3, bs);
            }
        }
        if (more) {
            __syncthreads();
            As[lkc+0][lrow]=a0.x; As[lkc+1][lrow]=a0.y; As[lkc+2][lrow]=a0.z; As[lkc+3][lrow]=a0.w;
            As[lkc+4][lrow]=a1.x; As[lkc+5][lrow]=a1.y; As[lkc+6][lrow]=a1.z; As[lkc+7][lrow]=a1.w;
            Bs[lkc+0][lrow]=b0.x; Bs[lkc+1][lrow]=b0.y; Bs[lkc+2][lrow]=b0.z; Bs[lkc+3][lrow]=b0.w;
            Bs[lkc+4][lrow]=b1.x; Bs[lkc+5][lrow]=b1.y; Bs[lkc+6][lrow]=b1.z; Bs[lkc+7][lrow]=b1.w;
            __syncthreads();
        }
    }

    float acc[8][8];
#pragma unroll
    for (int j = 0; j < 8; j++)
#pragma unroll
        for (int p = 0; p < 4; p++)
            unpack2(acc2[j][p], acc[2*p][j], acc[2*p+1][j]);

    float4 bb0 = {0,0,0,0}, bb1 = {0,0,0,0};
    if (HASBIAS) {
        bb0 = *(const float4*)(bias + bn + col0);
        bb1 = *(const float4*)(bias + bn + col0 + 4);
    }
#pragma unroll
    for (int i = 0; i < 8; i++) {
        const int r = bm + row0 + i;
        float4 o0 = { acc[i][0] + bb0.x, acc[i][1] + bb0.y, acc[i][2] + bb0.z, acc[i][3] + bb0.w };
        float4 o1 = { acc[i][4] + bb1.x, acc[i][5] + bb1.y, acc[i][6] + bb1.z, acc[i][7] + bb1.w };
        *(float4*)(C + (size_t)r * ldc + bn + col0)     = o0;
        *(float4*)(C + (size_t)r * ldc + bn + col0 + 4) = o1;
    }
}

// =====================================================================================
// gemm2 fused (scalar FFMA mainloop — measured best): A = relu(sum 4 partials + b1),
// C = A @ w2^T + b2 -> g_q, epilogue computes per-block BN column sums/sumsq.
// =====================================================================================
__global__ void __launch_bounds__(256) gemm2_fused(const float* __restrict__ b1,
                                                   const float* __restrict__ w2,
                                                   const float* __restrict__ b2)
{
    __shared__ float As[16][132];
    __shared__ float Bs[16][132];
    __shared__ float red[16][128];
    const int tid = threadIdx.x;
    const int bm = blockIdx.x * 128, bn = blockIdx.y * 128;

    const int lrow = tid >> 1;
    const int lkc  = (tid & 1) << 3;
    const size_t pstride = (size_t)N_TOK * C1;
    const float* Pptr = g_c1part + (size_t)(bm + lrow) * C1 + lkc;
    const float* Bptr = w2 + (size_t)(bn + lrow) * C1 + lkc;

    const int w = tid >> 5, lane = tid & 31;
    const int wr = w & 3, wc = w >> 2;
    const int row0 = (wr << 5) + ((lane & 3) << 3);
    const int col0 = (wc << 6) + ((lane >> 2) << 3);

    float acc[8][8] = {};
    float4 a0, a1, b0, b1v;

    auto loadA = [&](int k0, float4& o0, float4& o1) {
        const float* p = Pptr + k0;
        float4 u0 = *(const float4*)(p);
        float4 u1 = *(const float4*)(p + 4);
        float4 v0 = *(const float4*)(p + pstride);
        float4 v1 = *(const float4*)(p + pstride + 4);
        float4 x0 = *(const float4*)(p + 2*pstride);
        float4 x1 = *(const float4*)(p + 2*pstride + 4);
        float4 y0 = *(const float4*)(p + 3*pstride);
        float4 y1 = *(const float4*)(p + 3*pstride + 4);
        float4 c0 = *(const float4*)(b1 + k0 + lkc);
        float4 c1 = *(const float4*)(b1 + k0 + lkc + 4);
        o0.x = fmaxf((u0.x+v0.x)+(x0.x+y0.x)+c0.x, 0.f);
        o0.y = fmaxf((u0.y+v0.y)+(x0.y+y0.y)+c0.y, 0.f);
        o0.z = fmaxf((u0.z+v0.z)+(x0.z+y0.z)+c0.z, 0.f);
        o0.w = fmaxf((u0.w+v0.w)+(x0.w+y0.w)+c0.w, 0.f);
        o1.x = fmaxf((u1.x+v1.x)+(x1.x+y1.x)+c1.x, 0.f);
        o1.y = fmaxf((u1.y+v1.y)+(x1.y+y1.y)+c1.y, 0.f);
        o1.z = fmaxf((u1.z+v1.z)+(x1.z+y1.z)+c1.z, 0.f);
        o1.w = fmaxf((u1.w+v1.w)+(x1.w+y1.w)+c1.w, 0.f);
    };

    loadA(0, a0, a1);
    b0 = *(const float4*)(Bptr);     b1v = *(const float4*)(Bptr + 4);
    As[lkc+0][lrow]=a0.x; As[lkc+1][lrow]=a0.y; As[lkc+2][lrow]=a0.z; As[lkc+3][lrow]=a0.w;
    As[lkc+4][lrow]=a1.x; As[lkc+5][lrow]=a1.y; As[lkc+6][lrow]=a1.z; As[lkc+7][lrow]=a1.w;
    Bs[lkc+0][lrow]=b0.x; Bs[lkc+1][lrow]=b0.y; Bs[lkc+2][lrow]=b0.z; Bs[lkc+3][lrow]=b0.w;
    Bs[lkc+4][lrow]=b1v.x; Bs[lkc+5][lrow]=b1v.y; Bs[lkc+6][lrow]=b1v.z; Bs[lkc+7][lrow]=b1v.w;
    __syncthreads();

#pragma unroll 1
    for (int kb = 1; kb <= C1 / 16; kb++) {
        const bool more = kb < C1 / 16;
        if (more) {
            const int k0 = kb * 16;
            loadA(k0, a0, a1);
            b0 = *(const float4*)(Bptr + k0);     b1v = *(const float4*)(Bptr + k0 + 4);
        }
#pragma unroll
        for (int k = 0; k < 16; k++) {
            float4 af0 = *(const float4*)&As[k][row0];
            float4 af1 = *(const float4*)&As[k][row0 + 4];
            float4 bf0 = *(const float4*)&Bs[k][col0];
            float4 bf1 = *(const float4*)&Bs[k][col0 + 4];
            const float ar[8] = {af0.x,af0.y,af0.z,af0.w,af1.x,af1.y,af1.z,af1.w};
            const float br[8] = {bf0.x,bf0.y,bf0.z,bf0.w,bf1.x,bf1.y,bf1.z,bf1.w};
#pragma unroll
            for (int i = 0; i < 8; i++)
#pragma unroll
                for (int j = 0; j < 8; j++)
                    acc[i][j] = fmaf(ar[i], br[j], acc[i][j]);
        }
        if (more) {
            __syncthreads();
            As[lkc+0][lrow]=a0.x; As[lkc+1][lrow]=a0.y; As[lkc+2][lrow]=a0.z; As[lkc+3][lrow]=a0.w;
            As[lkc+4][lrow]=a1.x; As[lkc+5][lrow]=a1.y; As[lkc+6][lrow]=a1.z; As[lkc+7][lrow]=a1.w;
            Bs[lkc+0][lrow]=b0.x; Bs[lkc+1][lrow]=b0.y; Bs[lkc+2][lrow]=b0.z; Bs[lkc+3][lrow]=b0.w;
            Bs[lkc+4][lrow]=b1v.x; Bs[lkc+5][lrow]=b1v.y; Bs[lkc+6][lrow]=b1v.z; Bs[lkc+7][lrow]=b1v.w;
            __syncthreads();
        }
    }

    float4 bb0 = *(const float4*)(b2 + bn + col0);
    float4 bb1 = *(const float4*)(b2 + bn + col0 + 4);
    float ps[8] = {}, ps2[8] = {};
#pragma unroll
    for (int i = 0; i < 8; i++) {
        const int r = bm + row0 + i;
        float4 o0 = { acc[i][0] + bb0.x, acc[i][1] + bb0.y, acc[i][2] + bb0.z, acc[i][3] + bb0.w };
        float4 o1 = { acc[i][4] + bb1.x, acc[i][5] + bb1.y, acc[i][6] + bb1.z, acc[i][7] + bb1.w };
        *(float4*)(g_q + (size_t)r * D2 + bn + col0)     = o0;
        *(float4*)(g_q + (size_t)r * D2 + bn + col0 + 4) = o1;
        ps[0] += o0.x; ps[1] += o0.y; ps[2] += o0.z; ps[3] += o0.w;
        ps[4] += o1.x; ps[5] += o1.y; ps[6] += o1.z; ps[7] += o1.w;
        ps2[0] += o0.x*o0.x; ps2[1] += o0.y*o0.y; ps2[2] += o0.z*o0.z; ps2[3] += o0.w*o0.w;
        ps2[4] += o1.x*o1.x; ps2[5] += o1.y*o1.y; ps2[6] += o1.z*o1.z; ps2[7] += o1.w*o1.w;
    }

    const int rrank = (wr << 2) | (lane & 3);
    __syncthreads();
#pragma unroll
    for (int j = 0; j < 8; j++) red[rrank][col0 + j] = ps[j];
    __syncthreads();
    if (tid < 128) {
        float v = 0.f;
#pragma unroll
        for (int r = 0; r < 16; r++) v += red[r][tid];
        g_bn2s[(size_t)(bn + tid) * 16 + blockIdx.x] = v;
    }
    __syncthreads();
#pragma unroll
    for (int j = 0; j < 8; j++) red[rrank][col0 + j] = ps2[j];
    __syncthreads();
    if (tid < 128) {
        float v = 0.f;
#pragma unroll
        for (int r = 0; r < 16; r++) v += red[r][tid];
        g_bn2q[(size_t)(bn + tid) * 16 + blockIdx.x] = v;
    }
}

// ---------------- BN finalize: fold 16 m-blocks x 4 head-columns ----------------
__global__ void __launch_bounds__(64) bn_finalize(const float* __restrict__ gamma,
                                                  const float* __restrict__ beta)
{
    const int d = blockIdx.x, t = threadIdx.x;
    const int hh = t >> 4, bi = t & 15;
    const int col = d + (hh << 8);
    float s  = g_bn2s[(size_t)col * 16 + bi];
    float s2 = g_bn2q[(size_t)col * 16 + bi];
#pragma unroll
    for (int o = 16; o > 0; o >>= 1) {
        s  += __shfl_xor_sync(0xffffffffu, s, o);
        s2 += __shfl_xor_sync(0xffffffffu, s2, o);
    }
    __shared__ float r1[2], r2[2];
    if ((t & 31) == 0) { r1[t >> 5] = s; r2[t >> 5] = s2; }
    __syncthreads();
    if (t == 0) {
        s  = r1[0] + r1[1];
        s2 = r2[0] + r2[1];
        const float inv = 1.0f / 8192.0f;
        float mean = s * inv;
        float var  = s2 * inv - mean * mean;
        float sc = rsqrtf(var + 1e-5f) * gamma[d];
        g_scale[d] = sc;
        g_shift[d] = beta[d] - mean * sc;
    }
}

// =====================================================================================
// two-level top-k + softmax, v3: per-lane bitonic pre-sort + tournament extraction.
// Keys: hi = ordu(value), lo = ~index  -> descending by value, ties -> smaller index
// (bit-identical selection to jax top_k semantics). Extraction = 2 REDUX per pick.
// =====================================================================================
__global__ void __launch_bounds__(64) topk_kernel()
{
    const int b = blockIdx.x;
    const int t = b >> 2, h = b & 3;
    const int w = threadIdx.x >> 5;
    const int lane = threadIdx.x & 31;

    __shared__ float sts[2][32];
    __shared__ int   sti[2][32];
    __shared__ unsigned int shi[2][32][16];
    __shared__ unsigned int slo[2][32][16];

    // ---- phase 1: per warp, top-32 of 512 (sorted) ----
    {
        const float* row = g_s + ((size_t)(h * 2 + w) * N_TOK + t) * SUBN;
        unsigned int vh[16], vl[16];
#pragma unroll
        for (int c = 0; c < 16; c++) {
            const int idx = lane + (c << 5);
            vh[c] = ordu(row[idx]);
            vl[c] = ~(unsigned int)idx;
        }
        // bitonic sort 16 elements, descending by (vh, vl); keys are unique
#pragma unroll
        for (int kk = 2; kk <= 16; kk <<= 1) {
#pragma unroll
            for (int jj = kk >> 1; jj > 0; jj >>= 1) {
#pragma unroll
                for (int i = 0; i < 16; i++) {
                    const int l = i ^ jj;
                    if (l > i) {
                        const bool up = ((i & kk) == 0);
                        const bool less = (vh[i] < vh[l]) || (vh[i] == vh[l] && vl[i] < vl[l]);
                        if (up == less) {
                            unsigned int th = vh[i]; vh[i] = vh[l]; vh[l] = th;
                            unsigned int tl = vl[i]; vl[i] = vl[l]; vl[l] = tl;
                        }
                    }
                }
            }
        }
        // spill sorted list; keep head in registers
#pragma unroll
        for (int c = 0; c < 16; c++) { shi[w][lane][c] = vh[c]; slo[w][lane][c] = vl[c]; }
        unsigned int head_hi = vh[0], head_lo = vl[0];
        int ptr = 0;
#pragma unroll 1
        for (int it = 0; it < 32; it++) {
            const unsigned int m1 = __reduce_max_sync(0xffffffffu, head_hi);
            const bool cand = (head_hi == m1);
            const unsigned int m2 = __reduce_max_sync(0xffffffffu, cand ? head_lo : 0u);
            if (lane == it) { sts[w][it] = unordu(m1); sti[w][it] = (int)(~m2 & 511u); }
            if (cand && head_lo == m2) {
                ptr++;
                if (ptr < 16) { head_hi = shi[w][lane][ptr]; head_lo = slo[w][lane][ptr]; }
                else          { head_hi = 0u; head_lo = 0u; }
            }
        }
    }
    __syncthreads();

    // ---- phase 2: warp 0 — 119 pruned pair sums, top-32, softmax ----
    if (w == 0) {
        unsigned int kh[4], kl[4];
#pragma unroll
        for (int q = 0; q < 4; q++) {
            const int s = lane + (q << 5);
            const int pp = c_pp[s];
            const int i = pp >> 8, j = pp & 0xff;
            const float sum = sts[0][i] + sts[1][j];
            kh[q] = (s < 119) ? ordu(sum) : 0u;
            kl[q] = ~(unsigned int)((i << 5) | j);
        }
        // sort-4 descending by (kh, kl): network (0,1)(2,3)(0,2)(1,3)(1,2)
        {
#define TK_CE(a, c) { \
            const bool less = (kh[a] < kh[c]) || (kh[a] == kh[c] && kl[a] < kl[c]); \
            if (less) { unsigned int th=kh[a]; kh[a]=kh[c]; kh[c]=th; \
                        unsigned int tl=kl[a]; kl[a]=kl[c]; kl[c]=tl; } }
            TK_CE(0,1) TK_CE(2,3) TK_CE(0,2) TK_CE(1,3) TK_CE(1,2)
#undef TK_CE
        }
        unsigned int selu = 0, sel_lo = 0;
#pragma unroll 1
        for (int it = 0; it < 32; it++) {
            const unsigned int m1 = __reduce_max_sync(0xffffffffu, kh[0]);
            const bool cand = (kh[0] == m1);
            const unsigned int m2 = __reduce_max_sync(0xffffffffu, cand ? kl[0] : 0u);
            if (lane == it) { selu = m1; sel_lo = m2; }
            if (cand && kl[0] == m2) {   // unique winner pops its head (shift)
                kh[0]=kh[1]; kh[1]=kh[2]; kh[2]=kh[3]; kh[3]=0u;
                kl[0]=kl[1]; kl[1]=kl[2]; kl[2]=kl[3]; kl[3]=0u;
            }
        }

        const float myv = unordu(selu);
        const unsigned int flat = ~sel_lo & 1023u;
        const int i = (int)(flat >> 5), j = (int)(flat & 31u);
        const int idx = sti[0][i] * SUBN + sti[1][j];

        const float mx = __shfl_sync(0xffffffffu, myv, 0);   // lane 0 holds the max
        float e = expf(myv - mx);
        float sum = e;
#pragma unroll
        for (int o = 16; o > 0; o >>= 1) sum += __shfl_xor_sync(0xffffffffu, sum, o);
        const size_t oo = (size_t)t * (HEADS * KNN) + h * KNN + lane;
        g_idx[oo] = idx;
        g_w[oo]   = e / sum;
    }
}

// ---------------- weighted gather from values table (MLP=8) ----------------
__global__ void __launch_bounds__(128) gather_kernel(const float* __restrict__ values)
{
    const int t = blockIdx.x;
    const int tid = threadIdx.x;
    __shared__ int   sidx[128];
    __shared__ float sw[128];
    sidx[tid] = g_idx[(size_t)t * 128 + tid];
    sw[tid]   = g_w[(size_t)t * 128 + tid];
    __syncthreads();

    const int col = tid << 2;
    float4 a0 = {0,0,0,0}, a1 = {0,0,0,0}, a2 = {0,0,0,0}, a3 = {0,0,0,0};
    float4 a4 = {0,0,0,0}, a5 = {0,0,0,0}, a6 = {0,0,0,0}, a7 = {0,0,0,0};
#pragma unroll
    for (int k = 0; k < 128; k += 8) {
        const float4 v0 = *(const float4*)(values + (size_t)sidx[k + 0] * HDIM + col);
        const float4 v1 = *(const float4*)(values + (size_t)sidx[k + 1] * HDIM + col);
        const float4 v2 = *(const float4*)(values + (size_t)sidx[k + 2] * HDIM + col);
        const float4 v3 = *(const float4*)(values + (size_t)sidx[k + 3] * HDIM + col);
        const float4 v4 = *(const float4*)(values + (size_t)sidx[k + 4] * HDIM + col);
        const float4 v5 = *(const float4*)(values + (size_t)sidx[k + 5] * HDIM + col);
        const float4 v6 = *(const float4*)(values + (size_t)sidx[k + 6] * HDIM + col);
        const float4 v7 = *(const float4*)(values + (size_t)sidx[k + 7] * HDIM + col);
        const float w0 = sw[k+0], w1 = sw[k+1], w2 = sw[k+2], w3 = sw[k+3];
        const float w4 = sw[k+4], w5 = sw[k+5], w6 = sw[k+6], w7 = sw[k+7];
        a0.x += w0*v0.x; a0.y += w0*v0.y; a0.z += w0*v0.z; a0.w += w0*v0.w;
        a1.x += w1*v1.x; a1.y += w1*v1.y; a1.z += w1*v1.z; a1.w += w1*v1.w;
        a2.x += w2*v2.x; a2.y += w2*v2.y; a2.z += w2*v2.z; a2.w += w2*v2.w;
        a3.x += w3*v3.x; a3.y += w3*v3.y; a3.z += w3*v3.z; a3.w += w3*v3.w;
        a4.x += w4*v4.x; a4.y += w4*v4.y; a4.z += w4*v4.z; a4.w += w4*v4.w;
        a5.x += w5*v5.x; a5.y += w5*v5.y; a5.z += w5*v5.z; a5.w += w5*v5.w;
        a6.x += w6*v6.x; a6.y += w6*v6.y; a6.z += w6*v6.z; a6.w += w6*v6.w;
        a7.x += w7*v7.x; a7.y += w7*v7.y; a7.z += w7*v7.z; a7.w += w7*v7.w;
    }
    float4 acc;
    acc.x = ((a0.x + a1.x) + (a2.x + a3.x)) + ((a4.x + a5.x) + (a6.x + a7.x));
    acc.y = ((a0.y + a1.y) + (a2.y + a3.y)) + ((a4.y + a5.y) + (a6.y + a7.y));
    acc.z = ((a0.z + a1.z) + (a2.z + a3.z)) + ((a4.z + a5.z) + (a6.z + a7.z));
    acc.w = ((a0.w + a1.w) + (a2.w + a3.w)) + ((a4.w + a5.w) + (a6.w + a7.w));
    *(float4*)(g_partial + (size_t)t * HDIM + col) = acc;
}

// ---------------- deterministic reduce over sequence ----------------
__global__ void __launch_bounds__(512) reduce_kernel(float* __restrict__ out)
{
    const int e = blockIdx.x * 512 + threadIdx.x;
    const int bb = e >> 9, c = e & 511;
    float s0 = 0.f, s1 = 0.f, s2 = 0.f, s3 = 0.f;
#pragma unroll
    for (int l = 0; l < 64; l += 4) {
        s0 += g_partial[(size_t)((bb << 6) + l + 0) * HDIM + c];
        s1 += g_partial[(size_t)((bb << 6) + l + 1) * HDIM + c];
        s2 += g_partial[(size_t)((bb << 6) + l + 2) * HDIM + c];
        s3 += g_partial[(size_t)((bb << 6) + l + 3) * HDIM + c];
    }
    out[e] = (s0 + s1) + (s2 + s3);
}

// ---------------- launch ----------------
extern "C" void kernel_launch(void* const* d_in, const int* in_sizes, int n_in,
                              void* d_out, int out_size)
{
    (void)in_sizes; (void)n_in; (void)out_size;
    const float* x        = (const float*)d_in[0];
    const float* w1       = (const float*)d_in[1];
    const float* b1       = (const float*)d_in[2];
    const float* w2       = (const float*)d_in[3];
    const float* b2       = (const float*)d_in[4];
    const float* bn_gamma = (const float*)d_in[5];
    const float* bn_beta  = (const float*)d_in[6];
    const float* keys     = (const float*)d_in[7];
    const float* values   = (const float*)d_in[8];
    float* out = (float*)d_out;

    float *d_q, *d_c1, *d_s;
    cudaGetSymbolAddress((void**)&d_q, g_q);
    cudaGetSymbolAddress((void**)&d_c1, g_c1part);
    cudaGetSymbolAddress((void**)&d_s, g_s);

    // 1) gemm1 split-K=4 -> partials [4][2048x256]
    sgemm128<128, HDIM, HDIM, false, false>
        <<<dim3(16, 2, 4), 256>>>(x, w1, nullptr, d_c1, C1, 128, 128, (size_t)N_TOK * C1);
    // 2) gemm2 fused (combine+relu on A, BN partials in epilogue) -> g_q
    gemm2_fused<<<dim3(16, 8), 256>>>(b1, w2, b2);
    // 3) BN finalize
    bn_finalize<<<KDIM, 64>>>(bn_gamma, bn_beta);
    // 4) scores with fused BN normalize  [8][2048][512]   <-- profiled slot
    sgemm128<HALFD, D2, HALFD, false, true>
        <<<dim3(16, 4, 8), 256>>>(d_q, keys, nullptr, d_s, SUBN,
                                  128, SUBN * HALFD, (size_t)N_TOK * SUBN);
    // 5) two-level top-k + softmax
    topk_kernel<<<N_TOK * HEADS, 64>>>();
    // 6) weighted gather
    gather_kernel<<<N_TOK, 128>>>(values);
    // 7) sum over sequence
    reduce_kernel<<<32, 512>>>(out);
}

// round 12
// speedup vs baseline: 1.1300x; 1.0001x over previous
#include <cuda_runtime.h>
#include <math.h>

#define N_TOK 2048
#define HDIM  512
#define C1    256
#define D2    1024
#define KDIM  256
#define HALFD 128
#define HEADS 4
#define SUBN  512
#define KNN   32

typedef unsigned long long u64t;

// packed fp32x2 FMA (sm_100+): d.lo += a.lo*b.lo, d.hi += a.hi*b.hi  (bit-exact fp32)
__device__ __forceinline__ u64t pack2(float lo, float hi) {
    u64t r; asm("mov.b64 %0, {%1, %2};" : "=l"(r) : "f"(lo), "f"(hi)); return r;
}
__device__ __forceinline__ void ffma2(u64t& d, u64t a, u64t b) {
    asm("fma.rn.f32x2 %0, %1, %2, %0;" : "+l"(d) : "l"(a), "l"(b));
}
__device__ __forceinline__ void unpack2(u64t v, float& lo, float& hi) {
    asm("mov.b64 {%0, %1}, %2;" : "=f"(lo), "=f"(hi) : "l"(v));
}

// ---------------- static device scratch (no allocations allowed) ----------------
__device__ float g_c1part[4 * N_TOK * C1];        // 8 MB split-K partials for gemm1
__device__ float g_q[N_TOK * D2];                 // 8 MB
__device__ float g_bn2s[D2 * 16];                 // per-(col,mblock) sums
__device__ float g_bn2q[D2 * 16];                 // per-(col,mblock) sumsq
__device__ float g_scale[KDIM];
__device__ float g_shift[KDIM];
__device__ float g_s[8u * N_TOK * SUBN];          // 32 MB scores [z][t][k]
__device__ int   g_idx[N_TOK * HEADS * KNN];
__device__ float g_w[N_TOK * HEADS * KNN];
__device__ float g_partial[N_TOK * HDIM];         // per-token gather result

// phase-2 slot table: 119 pruned pairs (i+1)*(j+1)<=32, packed (i<<8)|j
__constant__ unsigned short c_pp[128] = {
    0x000,0x001,0x002,0x003,0x004,0x005,0x006,0x007,
    0x008,0x009,0x00A,0x00B,0x00C,0x00D,0x00E,0x00F,
    0x010,0x011,0x012,0x013,0x014,0x015,0x016,0x017,
    0x018,0x019,0x01A,0x01B,0x01C,0x01D,0x01E,0x01F,
    0x100,0x101,0x102,0x103,0x104,0x105,0x106,0x107,
    0x108,0x109,0x10A,0x10B,0x10C,0x10D,0x10E,0x10F,
    0x200,0x201,0x202,0x203,0x204,0x205,0x206,0x207,0x208,0x209,
    0x300,0x301,0x302,0x303,0x304,0x305,0x306,0x307,
    0x400,0x401,0x402,0x403,0x404,0x405,
    0x500,0x501,0x502,0x503,0x504,
    0x600,0x601,0x602,0x603,
    0x700,0x701,0x702,0x703,
    0x800,0x801,0x802,
    0x900,0x901,0x902,
    0xA00,0xA01,0xB00,0xB01,0xC00,0xC01,0xD00,0xD01,0xE00,0xE01,0xF00,0xF01,
    0x1000,0x1100,0x1200,0x1300,0x1400,0x1500,0x1600,0x1700,
    0x1800,0x1900,0x1A00,0x1B00,0x1C00,0x1D00,0x1E00,0x1F00,
    0,0,0,0,0,0,0,0,0
};

// order-preserving float<->uint transform
__device__ __forceinline__ unsigned int ordu(float f) {
    int s = __float_as_int(f);
    return (unsigned int)(s ^ ((s >> 31) | 0x80000000));
}
__device__ __forceinline__ float unordu(unsigned int u) {
    int s = (u & 0x80000000u) ? (int)(u ^ 0x80000000u) : (int)~u;
    return __int_as_float(s);
}

// =====================================================================================
// 128x128 tile SGEMM (R9/R11 measured-best): 256 threads, 8x8 microtile via FFMA2,
// BK=16, single-buffered smem, conflict-free 32x64 warp tile, __launch_bounds__(256,2).
// =====================================================================================
template<int K, int LDA, int LDB, bool HASBIAS, bool NORM>
__global__ void __launch_bounds__(256, 2) sgemm128(const float* __restrict__ A,
                                                   const float* __restrict__ B,
                                                   const float* __restrict__ bias,
                                                   float* __restrict__ C,
                                                   int ldc, int aZ, int bZ, size_t cZ)
{
    __shared__ float As[16][132];
    __shared__ float Bs[16][132];
    const int tid = threadIdx.x;
    const int z = blockIdx.z;
    const int bm = blockIdx.x * 128, bn = blockIdx.y * 128;
    A += (size_t)z * aZ;
    B += (size_t)z * bZ;
    C += (size_t)z * cZ;

    const int lrow = tid >> 1;
    const int lkc  = (tid & 1) << 3;
    const float* Aptr = A + (size_t)(bm + lrow) * LDA + lkc;
    const float* Bptr = B + (size_t)(bn + lrow) * LDB + lkc;

    const int w = tid >> 5, lane = tid & 31;
    const int wr = w & 3, wc = w >> 2;
    const int row0 = (wr << 5) + ((lane & 3) << 3);    // 0..120
    const int col0 = (wc << 6) + ((lane >> 2) << 3);   // 0..120

    u64t acc2[8][4];
#pragma unroll
    for (int j = 0; j < 8; j++)
#pragma unroll
        for (int p = 0; p < 4; p++) acc2[j][p] = 0ull;

    float4 a0, a1, b0, b1;

    a0 = *(const float4*)(Aptr);     a1 = *(const float4*)(Aptr + 4);
    b0 = *(const float4*)(Bptr);     b1 = *(const float4*)(Bptr + 4);
    if (NORM) {
        const int dk = ((z & 1) << 7) + lkc;
        float4 sc0 = *(const float4*)(g_scale + dk), sh0 = *(const float4*)(g_shift + dk);
        float4 sc1 = *(const float4*)(g_scale + dk + 4), sh1 = *(const float4*)(g_shift + dk + 4);
        a0.x = fmaf(a0.x, sc0.x, sh0.x); a0.y = fmaf(a0.y, sc0.y, sh0.y);
        a0.z = fmaf(a0.z, sc0.z, sh0.z); a0.w = fmaf(a0.w, sc0.w, sh0.w);
        a1.x = fmaf(a1.x, sc1.x, sh1.x); a1.y = fmaf(a1.y, sc1.y, sh1.y);
        a1.z = fmaf(a1.z, sc1.z, sh1.z); a1.w = fmaf(a1.w, sc1.w, sh1.w);
    }
    As[lkc+0][lrow]=a0.x; As[lkc+1][lrow]=a0.y; As[lkc+2][lrow]=a0.z; As[lkc+3][lrow]=a0.w;
    As[lkc+4][lrow]=a1.x; As[lkc+5][lrow]=a1.y; As[lkc+6][lrow]=a1.z; As[lkc+7][lrow]=a1.w;
    Bs[lkc+0][lrow]=b0.x; Bs[lkc+1][lrow]=b0.y; Bs[lkc+2][lrow]=b0.z; Bs[lkc+3][lrow]=b0.w;
    Bs[lkc+4][lrow]=b1.x; Bs[lkc+5][lrow]=b1.y; Bs[lkc+6][lrow]=b1.z; Bs[lkc+7][lrow]=b1.w;
    __syncthreads();

#pragma unroll 1
    for (int kb = 1; kb <= K / 16; kb++) {
        const bool more = kb < K / 16;
        if (more) {
            const int k0 = kb * 16;
            a0 = *(const float4*)(Aptr + k0);     a1 = *(const float4*)(Aptr + k0 + 4);
            b0 = *(const float4*)(Bptr + k0);     b1 = *(const float4*)(Bptr + k0 + 4);
            if (NORM) {
                const int dk = ((z & 1) << 7) + lkc + k0;
                float4 sc0 = *(const float4*)(g_scale + dk), sh0 = *(const float4*)(g_shift + dk);
                float4 sc1 = *(const float4*)(g_scale + dk + 4), sh1 = *(const float4*)(g_shift + dk + 4);
                a0.x = fmaf(a0.x, sc0.x, sh0.x); a0.y = fmaf(a0.y, sc0.y, sh0.y);
                a0.z = fmaf(a0.z, sc0.z, sh0.z); a0.w = fmaf(a0.w, sc0.w, sh0.w);
                a1.x = fmaf(a1.x, sc1.x, sh1.x); a1.y = fmaf(a1.y, sc1.y, sh1.y);
                a1.z = fmaf(a1.z, sc1.z, sh1.z); a1.w = fmaf(a1.w, sc1.w, sh1.w);
            }
        }
#pragma unroll
        for (int k = 0; k < 16; k++) {
            const u64t* ap0 = (const u64t*)&As[k][row0];
            const u64t* ap1 = (const u64t*)&As[k][row0 + 4];
            const u64t apair0 = ap0[0], apair1 = ap0[1], apair2 = ap1[0], apair3 = ap1[1];
            float4 bf0 = *(const float4*)&Bs[k][col0];
            float4 bf1 = *(const float4*)&Bs[k][col0 + 4];
            const float br[8] = {bf0.x,bf0.y,bf0.z,bf0.w,bf1.x,bf1.y,bf1.z,bf1.w};
#pragma unroll
            for (int j = 0; j < 8; j++) {
                const u64t bs = pack2(br[j], br[j]);
                ffma2(acc2[j][0], apair0, bs);
                ffma2(acc2[j][1], apair1, bs);
                ffma2(acc2[j][2], apair2, bs);
                ffma2(acc2[j][3], apair3, bs);
            }
        }
        if (more) {
            __syncthreads();
            As[lkc+0][lrow]=a0.x; As[lkc+1][lrow]=a0.y; As[lkc+2][lrow]=a0.z; As[lkc+3][lrow]=a0.w;
            As[lkc+4][lrow]=a1.x; As[lkc+5][lrow]=a1.y; As[lkc+6][lrow]=a1.z; As[lkc+7][lrow]=a1.w;
            Bs[lkc+0][lrow]=b0.x; Bs[lkc+1][lrow]=b0.y; Bs[lkc+2][lrow]=b0.z; Bs[lkc+3][lrow]=b0.w;
            Bs[lkc+4][lrow]=b1.x; Bs[lkc+5][lrow]=b1.y; Bs[lkc+6][lrow]=b1.z; Bs[lkc+7][lrow]=b1.w;
            __syncthreads();
        }
    }

    float acc[8][8];
#pragma unroll
    for (int j = 0; j < 8; j++)
#pragma unroll
        for (int p = 0; p < 4; p++)
            unpack2(acc2[j][p], acc[2*p][j], acc[2*p+1][j]);

    float4 bb0 = {0,0,0,0}, bb1 = {0,0,0,0};
    if (HASBIAS) {
        bb0 = *(const float4*)(bias + bn + col0);
        bb1 = *(const float4*)(bias + bn + col0 + 4);
    }
#pragma unroll
    for (int i = 0; i < 8; i++) {
        const int r = bm + row0 + i;
        float4 o0 = { acc[i][0] + bb0.x, acc[i][1] + bb0.y, acc[i][2] + bb0.z, acc[i][3] + bb0.w };
        float4 o1 = { acc[i][4] + bb1.x, acc[i][5] + bb1.y, acc[i][6] + bb1.z, acc[i][7] + bb1.w };
        *(float4*)(C + (size_t)r * ldc + bn + col0)     = o0;
        *(float4*)(C + (size_t)r * ldc + bn + col0 + 4) = o1;
    }
}

// =====================================================================================
// gemm2 fused, now with FFMA2 + __launch_bounds__(256,2) (R9-proven recipe):
// A = relu(sum of 4 split-K partials + b1) on the fly, C = A @ w2^T + b2 -> g_q,
// epilogue computes per-block BN column sums/sumsq. loadA accumulates pairwise to
// limit live temps under the 128-reg cap.
// =====================================================================================
__global__ void __launch_bounds__(256, 2) gemm2_fused(const float* __restrict__ b1,
                                                      const float* __restrict__ w2,
                                                      const float* __restrict__ b2)
{
    __shared__ float As[16][132];
    __shared__ float Bs[16][132];
    __shared__ float red[16][128];
    const int tid = threadIdx.x;
    const int bm = blockIdx.x * 128, bn = blockIdx.y * 128;

    const int lrow = tid >> 1;
    const int lkc  = (tid & 1) << 3;
    const size_t pstride = (size_t)N_TOK * C1;
    const float* Pptr = g_c1part + (size_t)(bm + lrow) * C1 + lkc;
    const float* Bptr = w2 + (size_t)(bn + lrow) * C1 + lkc;

    const int w = tid >> 5, lane = tid & 31;
    const int wr = w & 3, wc = w >> 2;
    const int row0 = (wr << 5) + ((lane & 3) << 3);
    const int col0 = (wc << 6) + ((lane >> 2) << 3);

    u64t acc2[8][4];
#pragma unroll
    for (int j = 0; j < 8; j++)
#pragma unroll
        for (int p = 0; p < 4; p++) acc2[j][p] = 0ull;

    float4 a0, a1, b0, b1v;

    // pairwise-accumulating A producer: relu(p0+p1+p2+p3 + b1)
    auto loadA = [&](int k0, float4& o0, float4& o1) {
        const float* p = Pptr + k0;
        float4 s0 = *(const float4*)(p);
        float4 s1 = *(const float4*)(p + 4);
        {
            float4 v0 = *(const float4*)(p + pstride);
            float4 v1 = *(const float4*)(p + pstride + 4);
            s0.x += v0.x; s0.y += v0.y; s0.z += v0.z; s0.w += v0.w;
            s1.x += v1.x; s1.y += v1.y; s1.z += v1.z; s1.w += v1.w;
        }
        float4 t0 = *(const float4*)(p + 2*pstride);
        float4 t1 = *(const float4*)(p + 2*pstride + 4);
        {
            float4 v0 = *(const float4*)(p + 3*pstride);
            float4 v1 = *(const float4*)(p + 3*pstride + 4);
            t0.x += v0.x; t0.y += v0.y; t0.z += v0.z; t0.w += v0.w;
            t1.x += v1.x; t1.y += v1.y; t1.z += v1.z; t1.w += v1.w;
        }
        float4 c0 = *(const float4*)(b1 + k0 + lkc);
        float4 c1 = *(const float4*)(b1 + k0 + lkc + 4);
        o0.x = fmaxf((s0.x + t0.x) + c0.x, 0.f);
        o0.y = fmaxf((s0.y + t0.y) + c0.y, 0.f);
        o0.z = fmaxf((s0.z + t0.z) + c0.z, 0.f);
        o0.w = fmaxf((s0.w + t0.w) + c0.w, 0.f);
        o1.x = fmaxf((s1.x + t1.x) + c1.x, 0.f);
        o1.y = fmaxf((s1.y + t1.y) + c1.y, 0.f);
        o1.z = fmaxf((s1.z + t1.z) + c1.z, 0.f);
        o1.w = fmaxf((s1.w + t1.w) + c1.w, 0.f);
    };

    loadA(0, a0, a1);
    b0 = *(const float4*)(Bptr);     b1v = *(const float4*)(Bptr + 4);
    As[lkc+0][lrow]=a0.x; As[lkc+1][lrow]=a0.y; As[lkc+2][lrow]=a0.z; As[lkc+3][lrow]=a0.w;
    As[lkc+4][lrow]=a1.x; As[lkc+5][lrow]=a1.y; As[lkc+6][lrow]=a1.z; As[lkc+7][lrow]=a1.w;
    Bs[lkc+0][lrow]=b0.x; Bs[lkc+1][lrow]=b0.y; Bs[lkc+2][lrow]=b0.z; Bs[lkc+3][lrow]=b0.w;
    Bs[lkc+4][lrow]=b1v.x; Bs[lkc+5][lrow]=b1v.y; Bs[lkc+6][lrow]=b1v.z; Bs[lkc+7][lrow]=b1v.w;
    __syncthreads();

#pragma unroll 1
    for (int kb = 1; kb <= C1 / 16; kb++) {
        const bool more = kb < C1 / 16;
        if (more) {
            const int k0 = kb * 16;
            loadA(k0, a0, a1);
            b0 = *(const float4*)(Bptr + k0);     b1v = *(const float4*)(Bptr + k0 + 4);
        }
#pragma unroll
        for (int k = 0; k < 16; k++) {
            const u64t* ap0 = (const u64t*)&As[k][row0];
            const u64t* ap1 = (const u64t*)&As[k][row0 + 4];
            const u64t apair0 = ap0[0], apair1 = ap0[1], apair2 = ap1[0], apair3 = ap1[1];
            float4 bf0 = *(const float4*)&Bs[k][col0];
            float4 bf1 = *(const float4*)&Bs[k][col0 + 4];
            const float br[8] = {bf0.x,bf0.y,bf0.z,bf0.w,bf1.x,bf1.y,bf1.z,bf1.w};
#pragma unroll
            for (int j = 0; j < 8; j++) {
                const u64t bs = pack2(br[j], br[j]);
                ffma2(acc2[j][0], apair0, bs);
                ffma2(acc2[j][1], apair1, bs);
                ffma2(acc2[j][2], apair2, bs);
                ffma2(acc2[j][3], apair3, bs);
            }
        }
        if (more) {
            __syncthreads();
            As[lkc+0][lrow]=a0.x; As[lkc+1][lrow]=a0.y; As[lkc+2][lrow]=a0.z; As[lkc+3][lrow]=a0.w;
            As[lkc+4][lrow]=a1.x; As[lkc+5][lrow]=a1.y; As[lkc+6][lrow]=a1.z; As[lkc+7][lrow]=a1.w;
            Bs[lkc+0][lrow]=b0.x; Bs[lkc+1][lrow]=b0.y; Bs[lkc+2][lrow]=b0.z; Bs[lkc+3][lrow]=b0.w;
            Bs[lkc+4][lrow]=b1v.x; Bs[lkc+5][lrow]=b1v.y; Bs[lkc+6][lrow]=b1v.z; Bs[lkc+7][lrow]=b1v.w;
            __syncthreads();
        }
    }

    float acc[8][8];
#pragma unroll
    for (int j = 0; j < 8; j++)
#pragma unroll
        for (int p = 0; p < 4; p++)
            unpack2(acc2[j][p], acc[2*p][j], acc[2*p+1][j]);

    float4 bb0 = *(const float4*)(b2 + bn + col0);
    float4 bb1 = *(const float4*)(b2 + bn + col0 + 4);
    float ps[8] = {}, ps2[8] = {};
#pragma unroll
    for (int i = 0; i < 8; i++) {
        const int r = bm + row0 + i;
        float4 o0 = { acc[i][0] + bb0.x, acc[i][1] + bb0.y, acc[i][2] + bb0.z, acc[i][3] + bb0.w };
        float4 o1 = { acc[i][4] + bb1.x, acc[i][5] + bb1.y, acc[i][6] + bb1.z, acc[i][7] + bb1.w };
        *(float4*)(g_q + (size_t)r * D2 + bn + col0)     = o0;
        *(float4*)(g_q + (size_t)r * D2 + bn + col0 + 4) = o1;
        ps[0] += o0.x; ps[1] += o0.y; ps[2] += o0.z; ps[3] += o0.w;
        ps[4] += o1.x; ps[5] += o1.y; ps[6] += o1.z; ps[7] += o1.w;
        ps2[0] += o0.x*o0.x; ps2[1] += o0.y*o0.y; ps2[2] += o0.z*o0.z; ps2[3] += o0.w*o0.w;
        ps2[4] += o1.x*o1.x; ps2[5] += o1.y*o1.y; ps2[6] += o1.z*o1.z; ps2[7] += o1.w*o1.w;
    }

    const int rrank = (wr << 2) | (lane & 3);
    __syncthreads();
#pragma unroll
    for (int j = 0; j < 8; j++) red[rrank][col0 + j] = ps[j];
    __syncthreads();
    if (tid < 128) {
        float v = 0.f;
#pragma unroll
        for (int r = 0; r < 16; r++) v += red[r][tid];
        g_bn2s[(size_t)(bn + tid) * 16 + blockIdx.x] = v;
    }
    __syncthreads();
#pragma unroll
    for (int j = 0; j < 8; j++) red[rrank][col0 + j] = ps2[j];
    __syncthreads();
    if (tid < 128) {
        float v = 0.f;
#pragma unroll
        for (int r = 0; r < 16; r++) v += red[r][tid];
        g_bn2q[(size_t)(bn + tid) * 16 + blockIdx.x] = v;
    }
}

// ---------------- BN finalize: fold 16 m-blocks x 4 head-columns ----------------
__global__ void __launch_bounds__(64) bn_finalize(const float* __restrict__ gamma,
                                                  const float* __restrict__ beta)
{
    const int d = blockIdx.x, t = threadIdx.x;
    const int hh = t >> 4, bi = t & 15;
    const int col = d + (hh << 8);
    float s  = g_bn2s[(size_t)col * 16 + bi];
    float s2 = g_bn2q[(size_t)col * 16 + bi];
#pragma unroll
    for (int o = 16; o > 0; o >>= 1) {
        s  += __shfl_xor_sync(0xffffffffu, s, o);
        s2 += __shfl_xor_sync(0xffffffffu, s2, o);
    }
    __shared__ float r1[2], r2[2];
    if ((t & 31) == 0) { r1[t >> 5] = s; r2[t >> 5] = s2; }
    __syncthreads();
    if (t == 0) {
        s  = r1[0] + r1[1];
        s2 = r2[0] + r2[1];
        const float inv = 1.0f / 8192.0f;
        float mean = s * inv;
        float var  = s2 * inv - mean * mean;
        float sc = rsqrtf(var + 1e-5f) * gamma[d];
        g_scale[d] = sc;
        g_shift[d] = beta[d] - mean * sc;
    }
}

// =====================================================================================
// two-level top-k + softmax (R11 measured-best): per-lane bitonic pre-sort +
// REDUX tournament. Keys (ordu(v), ~idx) -> exact jax tie-break.
// =====================================================================================
__global__ void __launch_bounds__(64) topk_kernel()
{
    const int b = blockIdx.x;
    const int t = b >> 2, h = b & 3;
    const int w = threadIdx.x >> 5;
    const int lane = threadIdx.x & 31;

    __shared__ float sts[2][32];
    __shared__ int   sti[2][32];
    __shared__ unsigned int shi[2][32][16];
    __shared__ unsigned int slo[2][32][16];

    // ---- phase 1: per warp, top-32 of 512 (sorted) ----
    {
        const float* row = g_s + ((size_t)(h * 2 + w) * N_TOK + t) * SUBN;
        unsigned int vh[16], vl[16];
#pragma unroll
        for (int c = 0; c < 16; c++) {
            const int idx = lane + (c << 5);
            vh[c] = ordu(row[idx]);
            vl[c] = ~(unsigned int)idx;
        }
        // bitonic sort 16 elements, descending by (vh, vl); keys are unique
#pragma unroll
        for (int kk = 2; kk <= 16; kk <<= 1) {
#pragma unroll
            for (int jj = kk >> 1; jj > 0; jj >>= 1) {
#pragma unroll
                for (int i = 0; i < 16; i++) {
                    const int l = i ^ jj;
                    if (l > i) {
                        const bool up = ((i & kk) == 0);
                        const bool less = (vh[i] < vh[l]) || (vh[i] == vh[l] && vl[i] < vl[l]);
                        if (up == less) {
                            unsigned int th = vh[i]; vh[i] = vh[l]; vh[l] = th;
                            unsigned int tl = vl[i]; vl[i] = vl[l]; vl[l] = tl;
                        }
                    }
                }
            }
        }
        // spill sorted list; keep head in registers
#pragma unroll
        for (int c = 0; c < 16; c++) { shi[w][lane][c] = vh[c]; slo[w][lane][c] = vl[c]; }
        unsigned int head_hi = vh[0], head_lo = vl[0];
        int ptr = 0;
#pragma unroll 1
        for (int it = 0; it < 32; it++) {
            const unsigned int m1 = __reduce_max_sync(0xffffffffu, head_hi);
            const bool cand = (head_hi == m1);
            const unsigned int m2 = __reduce_max_sync(0xffffffffu, cand ? head_lo : 0u);
            if (lane == it) { sts[w][it] = unordu(m1); sti[w][it] = (int)(~m2 & 511u); }
            if (cand && head_lo == m2) {
                ptr++;
                if (ptr < 16) { head_hi = shi[w][lane][ptr]; head_lo = slo[w][lane][ptr]; }
                else          { head_hi = 0u; head_lo = 0u; }
            }
        }
    }
    __syncthreads();

    // ---- phase 2: warp 0 — 119 pruned pair sums, top-32, softmax ----
    if (w == 0) {
        unsigned int kh[4], kl[4];
#pragma unroll
        for (int q = 0; q < 4; q++) {
            const int s = lane + (q << 5);
            const int pp = c_pp[s];
            const int i = pp >> 8, j = pp & 0xff;
            const float sum = sts[0][i] + sts[1][j];
            kh[q] = (s < 119) ? ordu(sum) : 0u;
            kl[q] = ~(unsigned int)((i << 5) | j);
        }
        // sort-4 descending by (kh, kl): network (0,1)(2,3)(0,2)(1,3)(1,2)
        {
#define TK_CE(a, c) { \
            const bool less = (kh[a] < kh[c]) || (kh[a] == kh[c] && kl[a] < kl[c]); \
            if (less) { unsigned int th=kh[a]; kh[a]=kh[c]; kh[c]=th; \
                        unsigned int tl=kl[a]; kl[a]=kl[c]; kl[c]=tl; } }
            TK_CE(0,1) TK_CE(2,3) TK_CE(0,2) TK_CE(1,3) TK_CE(1,2)
#undef TK_CE
        }
        unsigned int selu = 0, sel_lo = 0;
#pragma unroll 1
        for (int it = 0; it < 32; it++) {
            const unsigned int m1 = __reduce_max_sync(0xffffffffu, kh[0]);
            const bool cand = (kh[0] == m1);
            const unsigned int m2 = __reduce_max_sync(0xffffffffu, cand ? kl[0] : 0u);
            if (lane == it) { selu = m1; sel_lo = m2; }
            if (cand && kl[0] == m2) {   // unique winner pops its head (shift)
                kh[0]=kh[1]; kh[1]=kh[2]; kh[2]=kh[3]; kh[3]=0u;
                kl[0]=kl[1]; kl[1]=kl[2]; kl[2]=kl[3]; kl[3]=0u;
            }
        }

        const float myv = unordu(selu);
        const unsigned int flat = ~sel_lo & 1023u;
        const int i = (int)(flat >> 5), j = (int)(flat & 31u);
        const int idx = sti[0][i] * SUBN + sti[1][j];

        const float mx = __shfl_sync(0xffffffffu, myv, 0);   // lane 0 holds the max
        float e = expf(myv - mx);
        float sum = e;
#pragma unroll
        for (int o = 16; o > 0; o >>= 1) sum += __shfl_xor_sync(0xffffffffu, sum, o);
        const size_t oo = (size_t)t * (HEADS * KNN) + h * KNN + lane;
        g_idx[oo] = idx;
        g_w[oo]   = e / sum;
    }
}

// ---------------- weighted gather from values table (MLP=8) ----------------
__global__ void __launch_bounds__(128) gather_kernel(const float* __restrict__ values)
{
    const int t = blockIdx.x;
    const int tid = threadIdx.x;
    __shared__ int   sidx[128];
    __shared__ float sw[128];
    sidx[tid] = g_idx[(size_t)t * 128 + tid];
    sw[tid]   = g_w[(size_t)t * 128 + tid];
    __syncthreads();

    const int col = tid << 2;
    float4 a0 = {0,0,0,0}, a1 = {0,0,0,0}, a2 = {0,0,0,0}, a3 = {0,0,0,0};
    float4 a4 = {0,0,0,0}, a5 = {0,0,0,0}, a6 = {0,0,0,0}, a7 = {0,0,0,0};
#pragma unroll
    for (int k = 0; k < 128; k += 8) {
        const float4 v0 = *(const float4*)(values + (size_t)sidx[k + 0] * HDIM + col);
        const float4 v1 = *(const float4*)(values + (size_t)sidx[k + 1] * HDIM + col);
        const float4 v2 = *(const float4*)(values + (size_t)sidx[k + 2] * HDIM + col);
        const float4 v3 = *(const float4*)(values + (size_t)sidx[k + 3] * HDIM + col);
        const float4 v4 = *(const float4*)(values + (size_t)sidx[k + 4] * HDIM + col);
        const float4 v5 = *(const float4*)(values + (size_t)sidx[k + 5] * HDIM + col);
        const float4 v6 = *(const float4*)(values + (size_t)sidx[k + 6] * HDIM + col);
        const float4 v7 = *(const float4*)(values + (size_t)sidx[k + 7] * HDIM + col);
        const float w0 = sw[k+0], w1 = sw[k+1], w2 = sw[k+2], w3 = sw[k+3];
        const float w4 = sw[k+4], w5 = sw[k+5], w6 = sw[k+6], w7 = sw[k+7];
        a0.x += w0*v0.x; a0.y += w0*v0.y; a0.z += w0*v0.z; a0.w += w0*v0.w;
        a1.x += w1*v1.x; a1.y += w1*v1.y; a1.z += w1*v1.z; a1.w += w1*v1.w;
        a2.x += w2*v2.x; a2.y += w2*v2.y; a2.z += w2*v2.z; a2.w += w2*v2.w;
        a3.x += w3*v3.x; a3.y += w3*v3.y; a3.z += w3*v3.z; a3.w += w3*v3.w;
        a4.x += w4*v4.x; a4.y += w4*v4.y; a4.z += w4*v4.z; a4.w += w4*v4.w;
        a5.x += w5*v5.x; a5.y += w5*v5.y; a5.z += w5*v5.z; a5.w += w5*v5.w;
        a6.x += w6*v6.x; a6.y += w6*v6.y; a6.z += w6*v6.z; a6.w += w6*v6.w;
        a7.x += w7*v7.x; a7.y += w7*v7.y; a7.z += w7*v7.z; a7.w += w7*v7.w;
    }
    float4 acc;
    acc.x = ((a0.x + a1.x) + (a2.x + a3.x)) + ((a4.x + a5.x) + (a6.x + a7.x));
    acc.y = ((a0.y + a1.y) + (a2.y + a3.y)) + ((a4.y + a5.y) + (a6.y + a7.y));
    acc.z = ((a0.z + a1.z) + (a2.z + a3.z)) + ((a4.z + a5.z) + (a6.z + a7.z));
    acc.w = ((a0.w + a1.w) + (a2.w + a3.w)) + ((a4.w + a5.w) + (a6.w + a7.w));
    *(float4*)(g_partial + (size_t)t * HDIM + col) = acc;
}

// ---------------- deterministic reduce over sequence ----------------
__global__ void __launch_bounds__(512) reduce_kernel(float* __restrict__ out)
{
    const int e = blockIdx.x * 512 + threadIdx.x;
    const int bb = e >> 9, c = e & 511;
    float s0 = 0.f, s1 = 0.f, s2 = 0.f, s3 = 0.f;
#pragma unroll
    for (int l = 0; l < 64; l += 4) {
        s0 += g_partial[(size_t)((bb << 6) + l + 0) * HDIM + c];
        s1 += g_partial[(size_t)((bb << 6) + l + 1) * HDIM + c];
        s2 += g_partial[(size_t)((bb << 6) + l + 2) * HDIM + c];
        s3 += g_partial[(size_t)((bb << 6) + l + 3) * HDIM + c];
    }
    out[e] = (s0 + s1) + (s2 + s3);
}

// ---------------- launch ----------------
extern "C" void kernel_launch(void* const* d_in, const int* in_sizes, int n_in,
                              void* d_out, int out_size)
{
    (void)in_sizes; (void)n_in; (void)out_size;
    const float* x        = (const float*)d_in[0];
    const float* w1       = (const float*)d_in[1];
    const float* b1       = (const float*)d_in[2];
    const float* w2       = (const float*)d_in[3];
    const float* b2       = (const float*)d_in[4];
    const float* bn_gamma = (const float*)d_in[5];
    const float* bn_beta  = (const float*)d_in[6];
    const float* keys     = (const float*)d_in[7];
    const float* values   = (const float*)d_in[8];
    float* out = (float*)d_out;

    float *d_q, *d_c1, *d_s;
    cudaGetSymbolAddress((void**)&d_q, g_q);
    cudaGetSymbolAddress((void**)&d_c1, g_c1part);
    cudaGetSymbolAddress((void**)&d_s, g_s);

    // 1) gemm1 split-K=4 -> partials [4][2048x256]
    sgemm128<128, HDIM, HDIM, false, false>
        <<<dim3(16, 2, 4), 256>>>(x, w1, nullptr, d_c1, C1, 128, 128, (size_t)N_TOK * C1);
    // 2) gemm2 fused (combine+relu on A, BN partials in epilogue) -> g_q
    gemm2_fused<<<dim3(16, 8), 256>>>(b1, w2, b2);
    // 3) BN finalize
    bn_finalize<<<KDIM, 64>>>(bn_gamma, bn_beta);
    // 4) scores with fused BN normalize  [8][2048][512]   <-- profiled slot
    sgemm128<HALFD, D2, HALFD, false, true>
        <<<dim3(16, 4, 8), 256>>>(d_q, keys, nullptr, d_s, SUBN,
                                  128, SUBN * HALFD, (size_t)N_TOK * SUBN);
    // 5) two-level top-k + softmax
    topk_kernel<<<N_TOK * HEADS, 64>>>();
    // 6) weighted gather
    gather_kernel<<<N_TOK, 128>>>(values);
    // 7) sum over sequence
    reduce_kernel<<<32, 512>>>(out);
}

// round 13
// speedup vs baseline: 1.1399x; 1.0088x over previous
#include <cuda_runtime.h>
#include <math.h>

#define N_TOK 2048
#define HDIM  512
#define C1    256
#define D2    1024
#define KDIM  256
#define HALFD 128
#define HEADS 4
#define SUBN  512
#define KNN   32

typedef unsigned long long u64t;

// packed fp32x2 FMA (sm_100+): d.lo += a.lo*b.lo, d.hi += a.hi*b.hi  (bit-exact fp32)
__device__ __forceinline__ u64t pack2(float lo, float hi) {
    u64t r; asm("mov.b64 %0, {%1, %2};" : "=l"(r) : "f"(lo), "f"(hi)); return r;
}
__device__ __forceinline__ void ffma2(u64t& d, u64t a, u64t b) {
    asm("fma.rn.f32x2 %0, %1, %2, %0;" : "+l"(d) : "l"(a), "l"(b));
}
__device__ __forceinline__ void unpack2(u64t v, float& lo, float& hi) {
    asm("mov.b64 {%0, %1}, %2;" : "=f"(lo), "=f"(hi) : "l"(v));
}

// ---------------- static device scratch (no allocations allowed) ----------------
__device__ float g_c1part[8 * N_TOK * C1];        // 16 MB split-K=8 partials for gemm1
__device__ float g_h[N_TOK * C1];                 // 2 MB
__device__ float g_qpart[2 * N_TOK * D2];         // 16 MB split-K=2 partials for gemm2
__device__ float g_q[N_TOK * D2];                 // 8 MB
__device__ float g_bnpart[2 * KDIM * 256];        // [stat][d][block]
__device__ float g_scale[KDIM];
__device__ float g_shift[KDIM];
__device__ float g_s[8u * N_TOK * SUBN];          // 32 MB scores [z][t][k]
__device__ int   g_idx[N_TOK * HEADS * KNN];
__device__ float g_w[N_TOK * HEADS * KNN];
__device__ float g_partial[N_TOK * HDIM];         // per-token gather result

// phase-2 slot table: 119 pruned pairs (i+1)*(j+1)<=32, packed (i<<8)|j
__constant__ unsigned short c_pp[128] = {
    0x000,0x001,0x002,0x003,0x004,0x005,0x006,0x007,
    0x008,0x009,0x00A,0x00B,0x00C,0x00D,0x00E,0x00F,
    0x010,0x011,0x012,0x013,0x014,0x015,0x016,0x017,
    0x018,0x019,0x01A,0x01B,0x01C,0x01D,0x01E,0x01F,
    0x100,0x101,0x102,0x103,0x104,0x105,0x106,0x107,
    0x108,0x109,0x10A,0x10B,0x10C,0x10D,0x10E,0x10F,
    0x200,0x201,0x202,0x203,0x204,0x205,0x206,0x207,0x208,0x209,
    0x300,0x301,0x302,0x303,0x304,0x305,0x306,0x307,
    0x400,0x401,0x402,0x403,0x404,0x405,
    0x500,0x501,0x502,0x503,0x504,
    0x600,0x601,0x602,0x603,
    0x700,0x701,0x702,0x703,
    0x800,0x801,0x802,
    0x900,0x901,0x902,
    0xA00,0xA01,0xB00,0xB01,0xC00,0xC01,0xD00,0xD01,0xE00,0xE01,0xF00,0xF01,
    0x1000,0x1100,0x1200,0x1300,0x1400,0x1500,0x1600,0x1700,
    0x1800,0x1900,0x1A00,0x1B00,0x1C00,0x1D00,0x1E00,0x1F00,
    0,0,0,0,0,0,0,0,0
};

// order-preserving float<->uint transform
__device__ __forceinline__ unsigned int ordu(float f) {
    int s = __float_as_int(f);
    return (unsigned int)(s ^ ((s >> 31) | 0x80000000));
}
__device__ __forceinline__ float unordu(unsigned int u) {
    int s = (u & 0x80000000u) ? (int)(u ^ 0x80000000u) : (int)~u;
    return __int_as_float(s);
}

// =====================================================================================
// 128x128 tile SGEMM (measured-best config): 256 threads, 8x8 microtile via FFMA2,
// BK=16, single-buffered smem, conflict-free 32x64 warp tile, __launch_bounds__(256,2).
// =====================================================================================
template<int K, int LDA, int LDB, bool HASBIAS, bool NORM>
__global__ void __launch_bounds__(256, 2) sgemm128(const float* __restrict__ A,
                                                   const float* __restrict__ B,
                                                   const float* __restrict__ bias,
                                                   float* __restrict__ C,
                                                   int ldc, int aZ, int bZ, size_t cZ)
{
    __shared__ float As[16][132];
    __shared__ float Bs[16][132];
    const int tid = threadIdx.x;
    const int z = blockIdx.z;
    const int bm = blockIdx.x * 128, bn = blockIdx.y * 128;
    A += (size_t)z * aZ;
    B += (size_t)z * bZ;
    C += (size_t)z * cZ;

    const int lrow = tid >> 1;
    const int lkc  = (tid & 1) << 3;
    const float* Aptr = A + (size_t)(bm + lrow) * LDA + lkc;
    const float* Bptr = B + (size_t)(bn + lrow) * LDB + lkc;

    const int w = tid >> 5, lane = tid & 31;
    const int wr = w & 3, wc = w >> 2;
    const int row0 = (wr << 5) + ((lane & 3) << 3);    // 0..120
    const int col0 = (wc << 6) + ((lane >> 2) << 3);   // 0..120

    u64t acc2[8][4];
#pragma unroll
    for (int j = 0; j < 8; j++)
#pragma unroll
        for (int p = 0; p < 4; p++) acc2[j][p] = 0ull;

    float4 a0, a1, b0, b1;

    a0 = *(const float4*)(Aptr);     a1 = *(const float4*)(Aptr + 4);
    b0 = *(const float4*)(Bptr);     b1 = *(const float4*)(Bptr + 4);
    if (NORM) {
        const int dk = ((z & 1) << 7) + lkc;
        float4 sc0 = *(const float4*)(g_scale + dk), sh0 = *(const float4*)(g_shift + dk);
        float4 sc1 = *(const float4*)(g_scale + dk + 4), sh1 = *(const float4*)(g_shift + dk + 4);
        a0.x = fmaf(a0.x, sc0.x, sh0.x); a0.y = fmaf(a0.y, sc0.y, sh0.y);
        a0.z = fmaf(a0.z, sc0.z, sh0.z); a0.w = fmaf(a0.w, sc0.w, sh0.w);
        a1.x = fmaf(a1.x, sc1.x, sh1.x); a1.y = fmaf(a1.y, sc1.y, sh1.y);
        a1.z = fmaf(a1.z, sc1.z, sh1.z); a1.w = fmaf(a1.w, sc1.w, sh1.w);
    }
    As[lkc+0][lrow]=a0.x; As[lkc+1][lrow]=a0.y; As[lkc+2][lrow]=a0.z; As[lkc+3][lrow]=a0.w;
    As[lkc+4][lrow]=a1.x; As[lkc+5][lrow]=a1.y; As[lkc+6][lrow]=a1.z; As[lkc+7][lrow]=a1.w;
    Bs[lkc+0][lrow]=b0.x; Bs[lkc+1][lrow]=b0.y; Bs[lkc+2][lrow]=b0.z; Bs[lkc+3][lrow]=b0.w;
    Bs[lkc+4][lrow]=b1.x; Bs[lkc+5][lrow]=b1.y; Bs[lkc+6][lrow]=b1.z; Bs[lkc+7][lrow]=b1.w;
    __syncthreads();

#pragma unroll 1
    for (int kb = 1; kb <= K / 16; kb++) {
        const bool more = kb < K / 16;
        if (more) {
            const int k0 = kb * 16;
            a0 = *(const float4*)(Aptr + k0);     a1 = *(const float4*)(Aptr + k0 + 4);
            b0 = *(const float4*)(Bptr + k0);     b1 = *(const float4*)(Bptr + k0 + 4);
            if (NORM) {
                const int dk = ((z & 1) << 7) + lkc + k0;
                float4 sc0 = *(const float4*)(g_scale + dk), sh0 = *(const float4*)(g_shift + dk);
                float4 sc1 = *(const float4*)(g_scale + dk + 4), sh1 = *(const float4*)(g_shift + dk + 4);
                a0.x = fmaf(a0.x, sc0.x, sh0.x); a0.y = fmaf(a0.y, sc0.y, sh0.y);
                a0.z = fmaf(a0.z, sc0.z, sh0.z); a0.w = fmaf(a0.w, sc0.w, sh0.w);
                a1.x = fmaf(a1.x, sc1.x, sh1.x); a1.y = fmaf(a1.y, sc1.y, sh1.y);
                a1.z = fmaf(a1.z, sc1.z, sh1.z); a1.w = fmaf(a1.w, sc1.w, sh1.w);
            }
        }
#pragma unroll
        for (int k = 0; k < 16; k++) {
            const u64t* ap0 = (const u64t*)&As[k][row0];
            const u64t* ap1 = (const u64t*)&As[k][row0 + 4];
            const u64t apair0 = ap0[0], apair1 = ap0[1], apair2 = ap1[0], apair3 = ap1[1];
            float4 bf0 = *(const float4*)&Bs[k][col0];
            float4 bf1 = *(const float4*)&Bs[k][col0 + 4];
            const float br[8] = {bf0.x,bf0.y,bf0.z,bf0.w,bf1.x,bf1.y,bf1.z,bf1.w};
#pragma unroll
            for (int j = 0; j < 8; j++) {
                const u64t bs = pack2(br[j], br[j]);
                ffma2(acc2[j][0], apair0, bs);
                ffma2(acc2[j][1], apair1, bs);
                ffma2(acc2[j][2], apair2, bs);
                ffma2(acc2[j][3], apair3, bs);
            }
        }
        if (more) {
            __syncthreads();
            As[lkc+0][lrow]=a0.x; As[lkc+1][lrow]=a0.y; As[lkc+2][lrow]=a0.z; As[lkc+3][lrow]=a0.w;
            As[lkc+4][lrow]=a1.x; As[lkc+5][lrow]=a1.y; As[lkc+6][lrow]=a1.z; As[lkc+7][lrow]=a1.w;
            Bs[lkc+0][lrow]=b0.x; Bs[lkc+1][lrow]=b0.y; Bs[lkc+2][lrow]=b0.z; Bs[lkc+3][lrow]=b0.w;
            Bs[lkc+4][lrow]=b1.x; Bs[lkc+5][lrow]=b1.y; Bs[lkc+6][lrow]=b1.z; Bs[lkc+7][lrow]=b1.w;
            __syncthreads();
        }
    }

    float acc[8][8];
#pragma unroll
    for (int j = 0; j < 8; j++)
#pragma unroll
        for (int p = 0; p < 4; p++)
            unpack2(acc2[j][p], acc[2*p][j], acc[2*p+1][j]);

    float4 bb0 = {0,0,0,0}, bb1 = {0,0,0,0};
    if (HASBIAS) {
        bb0 = *(const float4*)(bias + bn + col0);
        bb1 = *(const float4*)(bias + bn + col0 + 4);
    }
#pragma unroll
    for (int i = 0; i < 8; i++) {
        const int r = bm + row0 + i;
        float4 o0 = { acc[i][0] + bb0.x, acc[i][1] + bb0.y, acc[i][2] + bb0.z, acc[i][3] + bb0.w };
        float4 o1 = { acc[i][4] + bb1.x, acc[i][5] + bb1.y, acc[i][6] + bb1.z, acc[i][7] + bb1.w };
        *(float4*)(C + (size_t)r * ldc + bn + col0)     = o0;
        *(float4*)(C + (size_t)r * ldc + bn + col0 + 4) = o1;
    }
}

// ---------------- split-K=8 combine for gemm1: g_h = relu(sum8 + b1) ----------------
__global__ void __launch_bounds__(256) combine_relu(const float* __restrict__ b1)
{
    const int i = blockIdx.x * 256 + threadIdx.x;      // f4 id, 131072 total
    const int c4 = (i & 63) << 2;
    const float4* p = (const float4*)g_c1part;
    const size_t stride = (size_t)N_TOK * C1 / 4;
    float4 s0 = p[i], s1 = p[i + stride];
    float4 s2 = p[i + 2*stride], s3 = p[i + 3*stride];
    float4 s4 = p[i + 4*stride], s5 = p[i + 5*stride];
    float4 s6 = p[i + 6*stride], s7 = p[i + 7*stride];
    float4 bb = *(const float4*)(b1 + c4);
    float4 o;
    o.x = fmaxf(((s0.x+s1.x)+(s2.x+s3.x)) + ((s4.x+s5.x)+(s6.x+s7.x)) + bb.x, 0.f);
    o.y = fmaxf(((s0.y+s1.y)+(s2.y+s3.y)) + ((s4.y+s5.y)+(s6.y+s7.y)) + bb.y, 0.f);
    o.z = fmaxf(((s0.z+s1.z)+(s2.z+s3.z)) + ((s4.z+s5.z)+(s6.z+s7.z)) + bb.z, 0.f);
    o.w = fmaxf(((s0.w+s1.w)+(s2.w+s3.w)) + ((s4.w+s5.w)+(s6.w+s7.w)) + bb.w, 0.f);
    ((float4*)g_h)[i] = o;
}

// ---------------- split-K=2 combine for gemm2: q = p0+p1+b2, plus BN partials --------
__global__ void __launch_bounds__(256) combine_q(const float* __restrict__ b2)
{
    const int b = blockIdx.x;          // 256 blocks, 32 rows of [8192][256] each
    const int t = threadIdx.x;
    const int dq = t & 63;             // float4 column 0..63
    const int rg = t >> 6;             // 0..3 row subgroup (8 rows each)
    const float4* P = (const float4*)g_qpart;
    const size_t stride = (size_t)N_TOK * D2 / 4;
    float4 s = {0,0,0,0}, s2 = {0,0,0,0};
#pragma unroll
    for (int i = 0; i < 8; i++) {
        const int r = b * 32 + rg * 8 + i;
        const size_t off = (size_t)r * 64 + dq;
        float4 v0 = P[off], v1 = P[off + stride];
        float4 bb = ((const float4*)b2)[(r & 3) * 64 + dq];
        float4 o = { v0.x + v1.x + bb.x, v0.y + v1.y + bb.y,
                     v0.z + v1.z + bb.z, v0.w + v1.w + bb.w };
        ((float4*)g_q)[off] = o;
        s.x += o.x; s.y += o.y; s.z += o.z; s.w += o.w;
        s2.x += o.x*o.x; s2.y += o.y*o.y; s2.z += o.z*o.z; s2.w += o.w*o.w;
    }
    __shared__ float4 sh1[256], sh2[256];
    sh1[t] = s; sh2[t] = s2;
    __syncthreads();
    if (rg == 0) {
        float4 x1 = sh1[dq + 64], x2 = sh1[dq + 128], x3 = sh1[dq + 192];
        s.x += x1.x + x2.x + x3.x; s.y += x1.y + x2.y + x3.y;
        s.z += x1.z + x2.z + x3.z; s.w += x1.w + x2.w + x3.w;
        float4 y1 = sh2[dq + 64], y2 = sh2[dq + 128], y3 = sh2[dq + 192];
        s2.x += y1.x + y2.x + y3.x; s2.y += y1.y + y2.y + y3.y;
        s2.z += y1.z + y2.z + y3.z; s2.w += y1.w + y2.w + y3.w;
        const int d = dq << 2;
        g_bnpart[(size_t)(d + 0) * 256 + b] = s.x;
        g_bnpart[(size_t)(d + 1) * 256 + b] = s.y;
        g_bnpart[(size_t)(d + 2) * 256 + b] = s.z;
        g_bnpart[(size_t)(d + 3) * 256 + b] = s.w;
        g_bnpart[(size_t)(KDIM + d + 0) * 256 + b] = s2.x;
        g_bnpart[(size_t)(KDIM + d + 1) * 256 + b] = s2.y;
        g_bnpart[(size_t)(KDIM + d + 2) * 256 + b] = s2.z;
        g_bnpart[(size_t)(KDIM + d + 3) * 256 + b] = s2.w;
    }
}

// ---------------- BN finalize: fold 256 block partials per dim ----------------
__global__ void __launch_bounds__(256) bn_finalize(const float* __restrict__ gamma,
                                                   const float* __restrict__ beta)
{
    const int d = blockIdx.x, t = threadIdx.x;
    float s  = g_bnpart[(size_t)d * 256 + t];
    float s2 = g_bnpart[(size_t)(KDIM + d) * 256 + t];
#pragma unroll
    for (int o = 16; o > 0; o >>= 1) {
        s  += __shfl_xor_sync(0xffffffffu, s, o);
        s2 += __shfl_xor_sync(0xffffffffu, s2, o);
    }
    __shared__ float r1[8], r2[8];
    if ((t & 31) == 0) { r1[t >> 5] = s; r2[t >> 5] = s2; }
    __syncthreads();
    if (t == 0) {
        s  = ((r1[0] + r1[1]) + (r1[2] + r1[3])) + ((r1[4] + r1[5]) + (r1[6] + r1[7]));
        s2 = ((r2[0] + r2[1]) + (r2[2] + r2[3])) + ((r2[4] + r2[5]) + (r2[6] + r2[7]));
        const float inv = 1.0f / 8192.0f;
        float mean = s * inv;
        float var  = s2 * inv - mean * mean;
        float sc = rsqrtf(var + 1e-5f) * gamma[d];
        g_scale[d] = sc;
        g_shift[d] = beta[d] - mean * sc;
    }
}

// =====================================================================================
// two-level top-k + softmax (R11 measured-best): per-lane bitonic pre-sort +
// REDUX tournament. Keys (ordu(v), ~idx) -> exact jax tie-break.
// =====================================================================================
__global__ void __launch_bounds__(64) topk_kernel()
{
    const int b = blockIdx.x;
    const int t = b >> 2, h = b & 3;
    const int w = threadIdx.x >> 5;
    const int lane = threadIdx.x & 31;

    __shared__ float sts[2][32];
    __shared__ int   sti[2][32];
    __shared__ unsigned int shi[2][32][16];
    __shared__ unsigned int slo[2][32][16];

    // ---- phase 1: per warp, top-32 of 512 (sorted) ----
    {
        const float* row = g_s + ((size_t)(h * 2 + w) * N_TOK + t) * SUBN;
        unsigned int vh[16], vl[16];
#pragma unroll
        for (int c = 0; c < 16; c++) {
            const int idx = lane + (c << 5);
            vh[c] = ordu(row[idx]);
            vl[c] = ~(unsigned int)idx;
        }
#pragma unroll
        for (int kk = 2; kk <= 16; kk <<= 1) {
#pragma unroll
            for (int jj = kk >> 1; jj > 0; jj >>= 1) {
#pragma unroll
                for (int i = 0; i < 16; i++) {
                    const int l = i ^ jj;
                    if (l > i) {
                        const bool up = ((i & kk) == 0);
                        const bool less = (vh[i] < vh[l]) || (vh[i] == vh[l] && vl[i] < vl[l]);
                        if (up == less) {
                            unsigned int th = vh[i]; vh[i] = vh[l]; vh[l] = th;
                            unsigned int tl = vl[i]; vl[i] = vl[l]; vl[l] = tl;
                        }
                    }
                }
            }
        }
#pragma unroll
        for (int c = 0; c < 16; c++) { shi[w][lane][c] = vh[c]; slo[w][lane][c] = vl[c]; }
        unsigned int head_hi = vh[0], head_lo = vl[0];
        int ptr = 0;
#pragma unroll 1
        for (int it = 0; it < 32; it++) {
            const unsigned int m1 = __reduce_max_sync(0xffffffffu, head_hi);
            const bool cand = (head_hi == m1);
            const unsigned int m2 = __reduce_max_sync(0xffffffffu, cand ? head_lo : 0u);
            if (lane == it) { sts[w][it] = unordu(m1); sti[w][it] = (int)(~m2 & 511u); }
            if (cand && head_lo == m2) {
                ptr++;
                if (ptr < 16) { head_hi = shi[w][lane][ptr]; head_lo = slo[w][lane][ptr]; }
                else          { head_hi = 0u; head_lo = 0u; }
            }
        }
    }
    __syncthreads();

    // ---- phase 2: warp 0 — 119 pruned pair sums, top-32, softmax ----
    if (w == 0) {
        unsigned int kh[4], kl[4];
#pragma unroll
        for (int q = 0; q < 4; q++) {
            const int s = lane + (q << 5);
            const int pp = c_pp[s];
            const int i = pp >> 8, j = pp & 0xff;
            const float sum = sts[0][i] + sts[1][j];
            kh[q] = (s < 119) ? ordu(sum) : 0u;
            kl[q] = ~(unsigned int)((i << 5) | j);
        }
        {
#define TK_CE(a, c) { \
            const bool less = (kh[a] < kh[c]) || (kh[a] == kh[c] && kl[a] < kl[c]); \
            if (less) { unsigned int th=kh[a]; kh[a]=kh[c]; kh[c]=th; \
                        unsigned int tl=kl[a]; kl[a]=kl[c]; kl[c]=tl; } }
            TK_CE(0,1) TK_CE(2,3) TK_CE(0,2) TK_CE(1,3) TK_CE(1,2)
#undef TK_CE
        }
        unsigned int selu = 0, sel_lo = 0;
#pragma unroll 1
        for (int it = 0; it < 32; it++) {
            const unsigned int m1 = __reduce_max_sync(0xffffffffu, kh[0]);
            const bool cand = (kh[0] == m1);
            const unsigned int m2 = __reduce_max_sync(0xffffffffu, cand ? kl[0] : 0u);
            if (lane == it) { selu = m1; sel_lo = m2; }
            if (cand && kl[0] == m2) {
                kh[0]=kh[1]; kh[1]=kh[2]; kh[2]=kh[3]; kh[3]=0u;
                kl[0]=kl[1]; kl[1]=kl[2]; kl[2]=kl[3]; kl[3]=0u;
            }
        }

        const float myv = unordu(selu);
        const unsigned int flat = ~sel_lo & 1023u;
        const int i = (int)(flat >> 5), j = (int)(flat & 31u);
        const int idx = sti[0][i] * SUBN + sti[1][j];

        const float mx = __shfl_sync(0xffffffffu, myv, 0);
        float e = expf(myv - mx);
        float sum = e;
#pragma unroll
        for (int o = 16; o > 0; o >>= 1) sum += __shfl_xor_sync(0xffffffffu, sum, o);
        const size_t oo = (size_t)t * (HEADS * KNN) + h * KNN + lane;
        g_idx[oo] = idx;
        g_w[oo]   = e / sum;
    }
}

// ---------------- weighted gather from values table (MLP=8) ----------------
__global__ void __launch_bounds__(128) gather_kernel(const float* __restrict__ values)
{
    const int t = blockIdx.x;
    const int tid = threadIdx.x;
    __shared__ int   sidx[128];
    __shared__ float sw[128];
    sidx[tid] = g_idx[(size_t)t * 128 + tid];
    sw[tid]   = g_w[(size_t)t * 128 + tid];
    __syncthreads();

    const int col = tid << 2;
    float4 a0 = {0,0,0,0}, a1 = {0,0,0,0}, a2 = {0,0,0,0}, a3 = {0,0,0,0};
    float4 a4 = {0,0,0,0}, a5 = {0,0,0,0}, a6 = {0,0,0,0}, a7 = {0,0,0,0};
#pragma unroll
    for (int k = 0; k < 128; k += 8) {
        const float4 v0 = *(const float4*)(values + (size_t)sidx[k + 0] * HDIM + col);
        const float4 v1 = *(const float4*)(values + (size_t)sidx[k + 1] * HDIM + col);
        const float4 v2 = *(const float4*)(values + (size_t)sidx[k + 2] * HDIM + col);
        const float4 v3 = *(const float4*)(values + (size_t)sidx[k + 3] * HDIM + col);
        const float4 v4 = *(const float4*)(values + (size_t)sidx[k + 4] * HDIM + col);
        const float4 v5 = *(const float4*)(values + (size_t)sidx[k + 5] * HDIM + col);
        const float4 v6 = *(const float4*)(values + (size_t)sidx[k + 6] * HDIM + col);
        const float4 v7 = *(const float4*)(values + (size_t)sidx[k + 7] * HDIM + col);
        const float w0 = sw[k+0], w1 = sw[k+1], w2 = sw[k+2], w3 = sw[k+3];
        const float w4 = sw[k+4], w5 = sw[k+5], w6 = sw[k+6], w7 = sw[k+7];
        a0.x += w0*v0.x; a0.y += w0*v0.y; a0.z += w0*v0.z; a0.w += w0*v0.w;
        a1.x += w1*v1.x; a1.y += w1*v1.y; a1.z += w1*v1.z; a1.w += w1*v1.w;
        a2.x += w2*v2.x; a2.y += w2*v2.y; a2.z += w2*v2.z; a2.w += w2*v2.w;
        a3.x += w3*v3.x; a3.y += w3*v3.y; a3.z += w3*v3.z; a3.w += w3*v3.w;
        a4.x += w4*v4.x; a4.y += w4*v4.y; a4.z += w4*v4.z; a4.w += w4*v4.w;
        a5.x += w5*v5.x; a5.y += w5*v5.y; a5.z += w5*v5.z; a5.w += w5*v5.w;
        a6.x += w6*v6.x; a6.y += w6*v6.y; a6.z += w6*v6.z; a6.w += w6*v6.w;
        a7.x += w7*v7.x; a7.y += w7*v7.y; a7.z += w7*v7.z; a7.w += w7*v7.w;
    }
    float4 acc;
    acc.x = ((a0.x + a1.x) + (a2.x + a3.x)) + ((a4.x + a5.x) + (a6.x + a7.x));
    acc.y = ((a0.y + a1.y) + (a2.y + a3.y)) + ((a4.y + a5.y) + (a6.y + a7.y));
    acc.z = ((a0.z + a1.z) + (a2.z + a3.z)) + ((a4.z + a5.z) + (a6.z + a7.z));
    acc.w = ((a0.w + a1.w) + (a2.w + a3.w)) + ((a4.w + a5.w) + (a6.w + a7.w));
    *(float4*)(g_partial + (size_t)t * HDIM + col) = acc;
}

// ---------------- deterministic reduce over sequence ----------------
__global__ void __launch_bounds__(512) reduce_kernel(float* __restrict__ out)
{
    const int e = blockIdx.x * 512 + threadIdx.x;
    const int bb = e >> 9, c = e & 511;
    float s0 = 0.f, s1 = 0.f, s2 = 0.f, s3 = 0.f;
#pragma unroll
    for (int l = 0; l < 64; l += 4) {
        s0 += g_partial[(size_t)((bb << 6) + l + 0) * HDIM + c];
        s1 += g_partial[(size_t)((bb << 6) + l + 1) * HDIM + c];
        s2 += g_partial[(size_t)((bb << 6) + l + 2) * HDIM + c];
        s3 += g_partial[(size_t)((bb << 6) + l + 3) * HDIM + c];
    }
    out[e] = (s0 + s1) + (s2 + s3);
}

// ---------------- launch ----------------
extern "C" void kernel_launch(void* const* d_in, const int* in_sizes, int n_in,
                              void* d_out, int out_size)
{
    (void)in_sizes; (void)n_in; (void)out_size;
    const float* x        = (const float*)d_in[0];
    const float* w1       = (const float*)d_in[1];
    const float* b1       = (const float*)d_in[2];
    const float* w2       = (const float*)d_in[3];
    const float* b2       = (const float*)d_in[4];
    const float* bn_gamma = (const float*)d_in[5];
    const float* bn_beta  = (const float*)d_in[6];
    const float* keys     = (const float*)d_in[7];
    const float* values   = (const float*)d_in[8];
    float* out = (float*)d_out;

    float *d_h, *d_q, *d_c1, *d_qp, *d_s;
    cudaGetSymbolAddress((void**)&d_h, g_h);
    cudaGetSymbolAddress((void**)&d_q, g_q);
    cudaGetSymbolAddress((void**)&d_c1, g_c1part);
    cudaGetSymbolAddress((void**)&d_qp, g_qpart);
    cudaGetSymbolAddress((void**)&d_s, g_s);

    // 1) gemm1 split-K=8 -> partials [8][2048x256]  (256 CTAs -> 2/SM occupancy works)
    sgemm128<64, HDIM, HDIM, false, false>
        <<<dim3(16, 2, 8), 256>>>(x, w1, nullptr, d_c1, C1, 64, 64, (size_t)N_TOK * C1);
    // 1b) combine + bias + relu -> g_h
    combine_relu<<<512, 256>>>(b1);
    // 2) gemm2 split-K=2 -> partials [2][2048x1024]  (256 CTAs)
    sgemm128<128, C1, C1, false, false>
        <<<dim3(16, 8, 2), 256>>>(d_h, w2, nullptr, d_qp, D2, 128, 128, (size_t)N_TOK * D2);
    // 2b) combine + bias -> g_q, BN partials
    combine_q<<<256, 256>>>(b2);
    // 3) BN finalize
    bn_finalize<<<KDIM, 256>>>(bn_gamma, bn_beta);
    // 4) scores with fused BN normalize  [8][2048][512]
    sgemm128<HALFD, D2, HALFD, false, true>
        <<<dim3(16, 4, 8), 256>>>(d_q, keys, nullptr, d_s, SUBN,
                                  128, SUBN * HALFD, (size_t)N_TOK * SUBN);
    // 5) two-level top-k + softmax
    topk_kernel<<<N_TOK * HEADS, 64>>>();
    // 6) weighted gather
    gather_kernel<<<N_TOK, 128>>>(values);
    // 7) sum over sequence
    reduce_kernel<<<32, 512>>>(out);
}